// round 2
// baseline (speedup 1.0000x reference)
#include <cuda_runtime.h>
#include <cuda_bf16.h>
#include <math.h>

// Problem constants
#define Bn 8
#define Tn 1024
#define En 1024
#define Hn 16
#define HDn 64
#define FFn 4096
#define E3n 3072
#define TOK 8192          // B*T
#define BHn 128           // B*H
#define SCALE_Q 0.125f    // 64^-0.5
#define LN_EPS 1e-12f

// ---------------- static scratch (no allocations allowed) ----------------
__device__ float g_qkv[TOK * E3n];                 // 100.7 MB
__device__ float g_scores[(long)BHn * Tn * Tn];    // 512 MB (scores then probs, in place)
__device__ float g_attn[TOK * En];                 // 33.5 MB
__device__ float g_tmp[TOK * En];                  // 33.5 MB
__device__ float g_x1[TOK * En];                   // 33.5 MB
__device__ float g_ffn[(long)TOK * FFn];           // 134 MB
__device__ int   g_len[Bn];

// ---------------- mask dtype detection + lengths ----------------
// self_padding_mask is [B,T] bool in the reference; harness dtype unknown.
// Classify from first 8192 bytes (safe for u8 / i32 / f32 interpretations):
//   any word == 0x3F800000            -> float32
//   else any word > 1                 -> byte-packed bool (u8)
//   else                              -> int32
__global__ void len_kernel(const void* maskp) {
    __shared__ int s_kind;   // 0=i32, 1=u8, 2=f32
    __shared__ int s_len[Bn];
    int t = threadIdx.x;
    if (t == 0) s_kind = 0;
    if (t < Bn) s_len[t] = Tn;
    __syncthreads();
    const unsigned int* w = (const unsigned int*)maskp;
    for (int i = t; i < 2048; i += blockDim.x) {   // first 8192 bytes
        unsigned int v = w[i];
        if (v == 0x3F800000u) atomicMax(&s_kind, 2);
        else if (v > 1u)      atomicMax(&s_kind, 1);
    }
    __syncthreads();
    int kind = s_kind;
    const unsigned char* mb = (const unsigned char*)maskp;
    const int* mi = (const int*)maskp;
    const float* mf = (const float*)maskp;
    for (int i = t; i < Bn * Tn; i += blockDim.x) {
        int b = i >> 10, tt = i & (Tn - 1);
        int m;
        if (kind == 1)      m = (int)mb[i];
        else if (kind == 2) m = (mf[i] != 0.0f);
        else                m = mi[i];
        if (m) atomicMin(&s_len[b], tt);
    }
    __syncthreads();
    if (t < Bn) g_len[t] = s_len[t];
}

// ---------------- big NT GEMM: C[M,N] = A[M,K] * W[N,K]^T + bias ----------------
// BM=BN=128, BK=8, 256 threads, 8x8 microtile. M,N divisible by 128, K by 8.
template<bool RELU>
__global__ void __launch_bounds__(256) gemm128(
    const float* __restrict__ A, int lda,
    const float* __restrict__ W, int ldb,
    const float* __restrict__ bias,
    float* __restrict__ C, int ldc, int K)
{
    __shared__ float As[8][132];
    __shared__ float Bs[8][132];
    int t = threadIdx.x;
    int m0 = blockIdx.y * 128, n0 = blockIdx.x * 128;
    int lrow = t >> 1;            // 0..127
    int seg  = (t & 1) * 4;       // 0 or 4
    const float* aptr = A + (long)(m0 + lrow) * lda + seg;
    const float* bptr = W + (long)(n0 + lrow) * ldb + seg;
    int ty = t >> 4, tx = t & 15;

    float acc[8][8];
#pragma unroll
    for (int i = 0; i < 8; i++)
#pragma unroll
        for (int j = 0; j < 8; j++) acc[i][j] = 0.0f;

    for (int k0 = 0; k0 < K; k0 += 8) {
        float4 av = *(const float4*)(aptr + k0);
        float4 bv = *(const float4*)(bptr + k0);
        __syncthreads();
        As[seg + 0][lrow] = av.x; As[seg + 1][lrow] = av.y;
        As[seg + 2][lrow] = av.z; As[seg + 3][lrow] = av.w;
        Bs[seg + 0][lrow] = bv.x; Bs[seg + 1][lrow] = bv.y;
        Bs[seg + 2][lrow] = bv.z; Bs[seg + 3][lrow] = bv.w;
        __syncthreads();
#pragma unroll
        for (int kk = 0; kk < 8; kk++) {
            float ar[8], br[8];
            *(float4*)&ar[0] = *(const float4*)&As[kk][ty * 8];
            *(float4*)&ar[4] = *(const float4*)&As[kk][ty * 8 + 4];
            *(float4*)&br[0] = *(const float4*)&Bs[kk][tx * 8];
            *(float4*)&br[4] = *(const float4*)&Bs[kk][tx * 8 + 4];
#pragma unroll
            for (int i = 0; i < 8; i++)
#pragma unroll
                for (int j = 0; j < 8; j++)
                    acc[i][j] = fmaf(ar[i], br[j], acc[i][j]);
        }
    }

    float bj[8];
#pragma unroll
    for (int j = 0; j < 8; j++) bj[j] = bias[n0 + tx * 8 + j];
#pragma unroll
    for (int i = 0; i < 8; i++) {
        int m = m0 + ty * 8 + i;
        float* crow = C + (long)m * ldc + n0 + tx * 8;
        float v[8];
#pragma unroll
        for (int j = 0; j < 8; j++) {
            float x = acc[i][j] + bj[j];
            if (RELU) x = fmaxf(x, 0.0f);
            v[j] = x;
        }
        *(float4*)&crow[0] = *(float4*)&v[0];
        *(float4*)&crow[4] = *(float4*)&v[4];
    }
}

// ---------------- attention scores: S[bh][q][k] = (q*SCALE) . k  ----------------
// grid: (T/64 k-tiles, T/64 q-tiles, B*H), 256 threads, 4x4 microtile, K=64 full.
__global__ void __launch_bounds__(256) scores_kernel(const float* __restrict__ qkv,
                                                     float* __restrict__ scores)
{
    int z = blockIdx.z;                 // b*H + h
    int b = z >> 4, h = z & 15;
    int q0 = blockIdx.y * 64, k0 = blockIdx.x * 64;
    if (k0 > q0 + 63) return;           // fully above causal diagonal

    __shared__ float Qs[64][65];
    __shared__ float Ks[64][65];
    int t = threadIdx.x;
    const float* qbase = qkv + (long)(b * Tn) * E3n + h * HDn;
    const float* kbase = qkv + (long)(b * Tn) * E3n + En + h * HDn;

    for (int i = t; i < 1024; i += 256) {
        int row = i >> 4, c4 = (i & 15) * 4;
        float4 qv = *(const float4*)(qbase + (long)(q0 + row) * E3n + c4);
        Qs[c4 + 0][row] = qv.x * SCALE_Q; Qs[c4 + 1][row] = qv.y * SCALE_Q;
        Qs[c4 + 2][row] = qv.z * SCALE_Q; Qs[c4 + 3][row] = qv.w * SCALE_Q;
        float4 kv = *(const float4*)(kbase + (long)(k0 + row) * E3n + c4);
        Ks[c4 + 0][row] = kv.x; Ks[c4 + 1][row] = kv.y;
        Ks[c4 + 2][row] = kv.z; Ks[c4 + 3][row] = kv.w;
    }
    __syncthreads();

    int ty = t >> 4, tx = t & 15;
    float acc[4][4];
#pragma unroll
    for (int i = 0; i < 4; i++)
#pragma unroll
        for (int j = 0; j < 4; j++) acc[i][j] = 0.0f;

#pragma unroll 8
    for (int kk = 0; kk < 64; kk++) {
        float a[4], bb[4];
#pragma unroll
        for (int i = 0; i < 4; i++) a[i] = Qs[kk][ty * 4 + i];
#pragma unroll
        for (int j = 0; j < 4; j++) bb[j] = Ks[kk][tx * 4 + j];
#pragma unroll
        for (int i = 0; i < 4; i++)
#pragma unroll
            for (int j = 0; j < 4; j++)
                acc[i][j] = fmaf(a[i], bb[j], acc[i][j]);
    }

#pragma unroll
    for (int i = 0; i < 4; i++) {
        long roff = ((long)z * Tn + (q0 + ty * 4 + i)) * Tn + k0 + tx * 4;
        *(float4*)&scores[roff] = *(float4*)&acc[i][0];
    }
}

// ---------------- masked softmax over each score row (in place) ----------------
__global__ void __launch_bounds__(256) softmax_kernel(float* __restrict__ scores)
{
    long z = blockIdx.x;                 // bh*T + q
    int q  = (int)(z & (Tn - 1));
    int bh = (int)(z >> 10);
    int b  = bh >> 4;
    float* row = scores + z * Tn;
    int kmax = min(q, g_len[b] - 1);     // valid key range is [0, kmax]

    int t = threadIdx.x;
    __shared__ float red[256];
    float vals[4];
    float lmax = -3.4e38f;
#pragma unroll
    for (int i = 0; i < 4; i++) {
        int k = t + i * 256;
        vals[i] = (k <= kmax) ? row[k] : -3.4e38f;
        lmax = fmaxf(lmax, vals[i]);
    }
    red[t] = lmax; __syncthreads();
    for (int s = 128; s > 0; s >>= 1) {
        if (t < s) red[t] = fmaxf(red[t], red[t + s]);
        __syncthreads();
    }
    float mx = red[0];
    __syncthreads();

    float lsum = 0.0f;
#pragma unroll
    for (int i = 0; i < 4; i++) {
        int k = t + i * 256;
        float e = (k <= kmax) ? expf(vals[i] - mx) : 0.0f;
        vals[i] = e;
        lsum += e;
    }
    red[t] = lsum; __syncthreads();
    for (int s = 128; s > 0; s >>= 1) {
        if (t < s) red[t] += red[t + s];
        __syncthreads();
    }
    float inv = 1.0f / red[0];
#pragma unroll
    for (int i = 0; i < 4; i++) {
        int k = t + i * 256;
        row[k] = vals[i] * inv;
    }
}

// ---------------- PV: attn[b][q][h*64+d] = sum_k P[bh][q][k] * V[b][k][h][d] ----------------
// grid: (1, T/64 q-tiles, B*H); BM=64 (q), BN=64 (d), BK=32 (keys)
__global__ void __launch_bounds__(256) pv_kernel(const float* __restrict__ qkv,
                                                 const float* __restrict__ p,
                                                 float* __restrict__ attn)
{
    int z = blockIdx.z, b = z >> 4, h = z & 15;
    int q0 = blockIdx.y * 64;
    __shared__ float Ps[32][65];
    __shared__ float Vs[32][64];
    int t = threadIdx.x, ty = t >> 4, tx = t & 15;
    const float* vbase = qkv + (long)(b * Tn) * E3n + 2 * En + h * HDn;
    const float* prow  = p + ((long)z * Tn + q0) * Tn;

    float acc[4][4];
#pragma unroll
    for (int i = 0; i < 4; i++)
#pragma unroll
        for (int j = 0; j < 4; j++) acc[i][j] = 0.0f;

    int kend = min(Tn, q0 + 64);        // probs are zero beyond the causal limit
    for (int kt = 0; kt < kend; kt += 32) {
        for (int i = t; i < 512; i += 256) {           // P tile 64q x 32k, transposed
            int row = i >> 3, c4 = (i & 7) * 4;
            float4 pv = *(const float4*)(prow + (long)row * Tn + kt + c4);
            Ps[c4 + 0][row] = pv.x; Ps[c4 + 1][row] = pv.y;
            Ps[c4 + 2][row] = pv.z; Ps[c4 + 3][row] = pv.w;
        }
        for (int i = t; i < 512; i += 256) {           // V tile 32k x 64d
            int row = i >> 4, c4 = (i & 15) * 4;
            float4 vv = *(const float4*)(vbase + (long)(kt + row) * E3n + c4);
            *(float4*)&Vs[row][c4] = vv;
        }
        __syncthreads();
#pragma unroll 8
        for (int kk = 0; kk < 32; kk++) {
            float a[4], bb[4];
#pragma unroll
            for (int i = 0; i < 4; i++) a[i] = Ps[kk][ty * 4 + i];
#pragma unroll
            for (int j = 0; j < 4; j++) bb[j] = Vs[kk][tx * 4 + j];
#pragma unroll
            for (int i = 0; i < 4; i++)
#pragma unroll
                for (int j = 0; j < 4; j++)
                    acc[i][j] = fmaf(a[i], bb[j], acc[i][j]);
        }
        __syncthreads();
    }

#pragma unroll
    for (int i = 0; i < 4; i++) {
        long off = ((long)(b * Tn) + q0 + ty * 4 + i) * En + h * HDn + tx * 4;
        *(float4*)&attn[off] = *(float4*)&acc[i][0];
    }
}

// ---------------- residual add + LayerNorm ----------------
__global__ void __launch_bounds__(256) ln_kernel(const float* __restrict__ res,
                                                 const float* __restrict__ y,
                                                 const float* __restrict__ w,
                                                 const float* __restrict__ bb,
                                                 float* __restrict__ out)
{
    long r = blockIdx.x;
    int t = threadIdx.x;
    const float* r0 = res + r * En;
    const float* y0 = y + r * En;
    __shared__ float rs[256], rss[256];
    float v[4];
    float s = 0.0f, ss = 0.0f;
#pragma unroll
    for (int i = 0; i < 4; i++) {
        int idx = t + i * 256;
        v[i] = r0[idx] + y0[idx];
        s += v[i];
        ss += v[i] * v[i];
    }
    rs[t] = s; rss[t] = ss; __syncthreads();
    for (int sh = 128; sh > 0; sh >>= 1) {
        if (t < sh) { rs[t] += rs[t + sh]; rss[t] += rss[t + sh]; }
        __syncthreads();
    }
    float mean = rs[0] * (1.0f / En);
    float var  = rss[0] * (1.0f / En) - mean * mean;
    float inv  = rsqrtf(var + LN_EPS);
#pragma unroll
    for (int i = 0; i < 4; i++) {
        int idx = t + i * 256;
        out[r * En + idx] = w[idx] * (v[i] - mean) * inv + bb[idx];
    }
}

// ---------------- launch ----------------
extern "C" void kernel_launch(void* const* d_in, const int* in_sizes, int n_in,
                              void* d_out, int out_size)
{
    const float* x     = (const float*)d_in[0];
    const float* in_w  = (const float*)d_in[1];
    const float* in_b  = (const float*)d_in[2];
    const float* out_w = (const float*)d_in[3];
    const float* out_b = (const float*)d_in[4];
    const float* fc1_w = (const float*)d_in[5];
    const float* fc1_b = (const float*)d_in[6];
    const float* fc2_w = (const float*)d_in[7];
    const float* fc2_b = (const float*)d_in[8];
    const float* ln1_w = (const float*)d_in[9];
    const float* ln1_b = (const float*)d_in[10];
    const float* ln2_w = (const float*)d_in[11];
    const float* ln2_b = (const float*)d_in[12];
    const void*  pad_mask = d_in[13];
    float* out = (float*)d_out;

    float *qkv, *scores, *attn, *tmp, *x1, *ffn;
    cudaGetSymbolAddress((void**)&qkv,    g_qkv);
    cudaGetSymbolAddress((void**)&scores, g_scores);
    cudaGetSymbolAddress((void**)&attn,   g_attn);
    cudaGetSymbolAddress((void**)&tmp,    g_tmp);
    cudaGetSymbolAddress((void**)&x1,     g_x1);
    cudaGetSymbolAddress((void**)&ffn,    g_ffn);

    // 0. sequence lengths from padding mask (dtype auto-detected)
    len_kernel<<<1, 256>>>(pad_mask);

    // 1. QKV projection: [8192,1024] x [3072,1024]^T -> [8192,3072]
    gemm128<false><<<dim3(E3n / 128, TOK / 128), 256>>>(x, En, in_w, En, in_b, qkv, E3n, En);

    // 2. attention scores (causal tiles only)
    scores_kernel<<<dim3(Tn / 64, Tn / 64, BHn), 256>>>(qkv, scores);

    // 3. masked softmax in place
    softmax_kernel<<<BHn * Tn, 256>>>(scores);

    // 4. P @ V -> attn [8192,1024]
    pv_kernel<<<dim3(1, Tn / 64, BHn), 256>>>(qkv, scores, attn);

    // 5. output projection
    gemm128<false><<<dim3(En / 128, TOK / 128), 256>>>(attn, En, out_w, En, out_b, tmp, En, En);

    // 6. residual + LN1 -> x1
    ln_kernel<<<TOK, 256>>>(x, tmp, ln1_w, ln1_b, x1);

    // 7. FC1 + ReLU: [8192,1024] x [4096,1024]^T -> [8192,4096]
    gemm128<true><<<dim3(FFn / 128, TOK / 128), 256>>>(x1, En, fc1_w, En, fc1_b, ffn, FFn, En);

    // 8. FC2: [8192,4096] x [1024,4096]^T -> [8192,1024]
    gemm128<false><<<dim3(En / 128, TOK / 128), 256>>>(ffn, FFn, fc2_w, FFn, fc2_b, tmp, En, FFn);

    // 9. residual + LN2 -> out
    ln_kernel<<<TOK, 256>>>(x1, tmp, ln2_w, ln2_b, out);
}

// round 4
// speedup vs baseline: 3.1050x; 3.1050x over previous
#include <cuda_runtime.h>
#include <cuda_fp16.h>
#include <stdint.h>
#include <math.h>

// Problem constants
#define Bn 8
#define Tn 1024
#define En 1024
#define Hn 16
#define HDn 64
#define FFn 4096
#define E3n 3072
#define TOK 8192          // B*T
#define BHn 128           // B*H
#define SCALE_Q 0.125f    // 64^-0.5
#define LN_EPS 1e-12f

// ======================= PTX helpers (sm_80+ features only) =======================
__device__ __forceinline__ uint32_t smem_u32(const void* p) {
    uint32_t a;
    asm("{ .reg .u64 t; cvta.to.shared.u64 t, %1; cvt.u32.u64 %0, t; }" : "=r"(a) : "l"(p));
    return a;
}
#define CP_ASYNC16(dst, src) \
    asm volatile("cp.async.cg.shared.global [%0], [%1], 16;" :: "r"(dst), "l"(src) : "memory")
#define CP_COMMIT() asm volatile("cp.async.commit_group;" ::: "memory")
#define CP_WAIT2()  asm volatile("cp.async.wait_group 2;" ::: "memory")
#define LDSM_X4(r0, r1, r2, r3, addr) \
    asm volatile("ldmatrix.sync.aligned.m8n8.x4.shared.b16 {%0,%1,%2,%3}, [%4];" \
        : "=r"(r0), "=r"(r1), "=r"(r2), "=r"(r3) : "r"(addr))
#define MMA16816(d, a, b) \
    asm volatile("mma.sync.aligned.m16n8k16.row.col.f32.f16.f16.f32 " \
        "{%0,%1,%2,%3}, {%4,%5,%6,%7}, {%8,%9}, {%0,%1,%2,%3};" \
        : "+f"((d)[0]), "+f"((d)[1]), "+f"((d)[2]), "+f"((d)[3]) \
        : "r"((a)[0]), "r"((a)[1]), "r"((a)[2]), "r"((a)[3]), "r"((b)[0]), "r"((b)[1]))

// ---------------- static scratch (no allocations allowed) ----------------
__device__ float g_qkv[TOK * E3n];                 // fp32 qkv for attention
__device__ float g_scores[(long)BHn * Tn * Tn];    // 512 MB
__device__ float g_tmp[TOK * En];
__device__ float g_x1[TOK * En];
__device__ int   g_len[Bn];
// fp16 hi/lo split operands (K doubled, interleaved)
__device__ __half g_xs[(long)TOK * 2 * En];
__device__ __half g_attns[(long)TOK * 2 * En];
__device__ __half g_x1s[(long)TOK * 2 * En];
__device__ __half g_ffns[(long)TOK * 2 * FFn];
__device__ __half g_inws[(long)E3n * 2 * En];
__device__ __half g_outws[(long)En * 2 * En];
__device__ __half g_fc1ws[(long)FFn * 2 * En];
__device__ __half g_fc2ws[(long)En * 2 * FFn];

// ---------------- fp32 -> interleaved fp16 hi/lo split ----------------
__global__ void __launch_bounds__(256) split_kernel(const float* __restrict__ src,
                                                    __half* __restrict__ dst, long n4)
{
    long i = (long)blockIdx.x * 256 + threadIdx.x;
    if (i >= n4) return;
    float4 v = ((const float4*)src)[i];
    __align__(16) __half o[8];
    float a; __half h;
    a = v.x; h = __float2half_rn(a); o[0] = h; o[1] = __float2half_rn(a - __half2float(h));
    a = v.y; h = __float2half_rn(a); o[2] = h; o[3] = __float2half_rn(a - __half2float(h));
    a = v.z; h = __float2half_rn(a); o[4] = h; o[5] = __float2half_rn(a - __half2float(h));
    a = v.w; h = __float2half_rn(a); o[6] = h; o[7] = __float2half_rn(a - __half2float(h));
    ((uint4*)dst)[i] = *(const uint4*)o;
}

// ---------------- mask dtype detection + lengths ----------------
__global__ void len_kernel(const void* maskp) {
    __shared__ int s_kind;   // 0=i32, 1=u8, 2=f32
    __shared__ int s_len[Bn];
    int t = threadIdx.x;
    if (t == 0) s_kind = 0;
    if (t < Bn) s_len[t] = Tn;
    __syncthreads();
    const unsigned int* w = (const unsigned int*)maskp;
    for (int i = t; i < 2048; i += blockDim.x) {
        unsigned int v = w[i];
        if (v == 0x3F800000u) atomicMax(&s_kind, 2);
        else if (v > 1u)      atomicMax(&s_kind, 1);
    }
    __syncthreads();
    int kind = s_kind;
    const unsigned char* mb = (const unsigned char*)maskp;
    const int* mi = (const int*)maskp;
    const float* mf = (const float*)maskp;
    for (int i = t; i < Bn * Tn; i += blockDim.x) {
        int b = i >> 10, tt = i & (Tn - 1);
        int m;
        if (kind == 1)      m = (int)mb[i];
        else if (kind == 2) m = (mf[i] != 0.0f);
        else                m = mi[i];
        if (m) atomicMin(&s_len[b], tt);
    }
    __syncthreads();
    if (t < Bn) g_len[t] = s_len[t];
}

// ============ mma.sync GEMM: C[M,N] = A2[M,K2](fp16) * B2[N,K2](fp16)^T + bias ============
// CTA 128x128, K-chunk 64 fp16 (128B rows, SW128 swizzle), 3-stage cp.async pipeline,
// 8 warps (2x4), warp tile 64x32 via m16n8k16. M,N multiples of 128, K2 multiple of 64.
#define GST 3
#define STAGE_BYTES 32768    // A 16KB + B 16KB

template<bool RELU, bool SPLIT_OUT>
__global__ void __launch_bounds__(256) gemm_mma(
    const __half* __restrict__ A2,
    const __half* __restrict__ B2,
    const float* __restrict__ bias,
    void* __restrict__ Cv, int N, int K2)
{
    extern __shared__ char smem[];
    uint32_t sb = smem_u32(smem);
    int tid = threadIdx.x, lane = tid & 31, w = tid >> 5;
    int m0 = blockIdx.y * 128, n0 = blockIdx.x * 128;
    int warpM = (w >> 2) * 64, warpN = (w & 3) * 32;
    const int CH = K2 >> 6;

    auto issue = [&](int c) {
        if (c < CH) {
            uint32_t base = sb + (c % GST) * STAGE_BYTES;
            long kb = (long)c * 64;
#pragma unroll
            for (int i = 0; i < 4; i++) {
                int flat = i * 256 + tid;
                int row = flat >> 3;
                int seg = flat & 7;
                uint32_t off = (uint32_t)(row * 128 + ((seg * 16) ^ ((row & 7) * 16)));
                CP_ASYNC16(base + off,         A2 + (long)(m0 + row) * K2 + kb + seg * 8);
                CP_ASYNC16(base + 16384 + off, B2 + (long)(n0 + row) * K2 + kb + seg * 8);
            }
        }
        CP_COMMIT();
    };
    issue(0); issue(1); issue(2);

    float acc[4][4][4];
#pragma unroll
    for (int i = 0; i < 4; i++)
#pragma unroll
        for (int j = 0; j < 4; j++)
#pragma unroll
            for (int k = 0; k < 4; k++) acc[i][j][k] = 0.0f;

    // ldmatrix per-thread row/col components
    int mrow = warpM + (lane & 7) + ((lane >> 3) & 1) * 8;   // + mi*16
    int acol = (lane >> 4) * 16;                             // k sub-block bytes (A)
    int nrow = warpN + (lane & 7) + ((lane >> 4) & 1) * 8;   // + nb*16
    int bcol = ((lane >> 3) & 1) * 16;                       // k sub-block bytes (B)

    for (int c = 0; c < CH; c++) {
        CP_WAIT2();
        __syncthreads();
        uint32_t sA = sb + (c % GST) * STAGE_BYTES;
        uint32_t sB = sA + 16384;
#pragma unroll
        for (int ks = 0; ks < 4; ks++) {
            uint32_t af[4][4];
#pragma unroll
            for (int mi = 0; mi < 4; mi++) {
                int m = mrow + mi * 16;
                uint32_t addr = sA + m * 128 + ((ks * 32 + acol) ^ ((m & 7) * 16));
                LDSM_X4(af[mi][0], af[mi][1], af[mi][2], af[mi][3], addr);
            }
            uint32_t bf[4][2];
#pragma unroll
            for (int nb = 0; nb < 2; nb++) {
                int n = nrow + nb * 16;
                uint32_t addr = sB + n * 128 + ((ks * 32 + bcol) ^ ((n & 7) * 16));
                uint32_t r0, r1, r2, r3;
                LDSM_X4(r0, r1, r2, r3, addr);
                bf[nb * 2][0] = r0;     bf[nb * 2][1] = r1;
                bf[nb * 2 + 1][0] = r2; bf[nb * 2 + 1][1] = r3;
            }
#pragma unroll
            for (int mi = 0; mi < 4; mi++)
#pragma unroll
                for (int ni = 0; ni < 4; ni++)
                    MMA16816(acc[mi][ni], af[mi], bf[ni]);
        }
        __syncthreads();
        issue(c + 3);
    }

    // epilogue
#pragma unroll
    for (int mi = 0; mi < 4; mi++) {
        int r = m0 + warpM + mi * 16 + (lane >> 2);
#pragma unroll
        for (int ni = 0; ni < 4; ni++) {
            int col = n0 + warpN + ni * 8 + (lane & 3) * 2;
            float b0 = bias[col], b1 = bias[col + 1];
            float v0 = acc[mi][ni][0] + b0, v1 = acc[mi][ni][1] + b1;
            float v2 = acc[mi][ni][2] + b0, v3 = acc[mi][ni][3] + b1;
            if (RELU) {
                v0 = fmaxf(v0, 0.0f); v1 = fmaxf(v1, 0.0f);
                v2 = fmaxf(v2, 0.0f); v3 = fmaxf(v3, 0.0f);
            }
            if (SPLIT_OUT) {
                __half* C = (__half*)Cv;
                __align__(8) __half o[4];
                __half h;
                h = __float2half_rn(v0); o[0] = h; o[1] = __float2half_rn(v0 - __half2float(h));
                h = __float2half_rn(v1); o[2] = h; o[3] = __float2half_rn(v1 - __half2float(h));
                *(uint2*)(C + (long)r * (2 * N) + 2 * col) = *(const uint2*)o;
                h = __float2half_rn(v2); o[0] = h; o[1] = __float2half_rn(v2 - __half2float(h));
                h = __float2half_rn(v3); o[2] = h; o[3] = __float2half_rn(v3 - __half2float(h));
                *(uint2*)(C + (long)(r + 8) * (2 * N) + 2 * col) = *(const uint2*)o;
            } else {
                float* C = (float*)Cv;
                float2 p0; p0.x = v0; p0.y = v1;
                float2 p1; p1.x = v2; p1.y = v3;
                *(float2*)(C + (long)r * N + col) = p0;
                *(float2*)(C + (long)(r + 8) * N + col) = p1;
            }
        }
    }
}

// ---------------- attention scores: S[bh][q][k] = (q*SCALE) . k ----------------
__global__ void __launch_bounds__(256) scores_kernel(const float* __restrict__ qkv,
                                                     float* __restrict__ scores)
{
    int z = blockIdx.z;                 // b*H + h
    int b = z >> 4, h = z & 15;
    int q0 = blockIdx.y * 64, k0 = blockIdx.x * 64;
    if (k0 > q0 + 63) return;           // fully above causal diagonal

    __shared__ float Qs[64][65];
    __shared__ float Ks[64][65];
    int t = threadIdx.x;
    const float* qbase = qkv + (long)(b * Tn) * E3n + h * HDn;
    const float* kbase = qkv + (long)(b * Tn) * E3n + En + h * HDn;

    for (int i = t; i < 1024; i += 256) {
        int row = i >> 4, c4 = (i & 15) * 4;
        float4 qv = *(const float4*)(qbase + (long)(q0 + row) * E3n + c4);
        Qs[c4 + 0][row] = qv.x * SCALE_Q; Qs[c4 + 1][row] = qv.y * SCALE_Q;
        Qs[c4 + 2][row] = qv.z * SCALE_Q; Qs[c4 + 3][row] = qv.w * SCALE_Q;
        float4 kv = *(const float4*)(kbase + (long)(k0 + row) * E3n + c4);
        Ks[c4 + 0][row] = kv.x; Ks[c4 + 1][row] = kv.y;
        Ks[c4 + 2][row] = kv.z; Ks[c4 + 3][row] = kv.w;
    }
    __syncthreads();

    int ty = t >> 4, tx = t & 15;
    float acc[4][4];
#pragma unroll
    for (int i = 0; i < 4; i++)
#pragma unroll
        for (int j = 0; j < 4; j++) acc[i][j] = 0.0f;

#pragma unroll 8
    for (int kk = 0; kk < 64; kk++) {
        float a[4], bb[4];
#pragma unroll
        for (int i = 0; i < 4; i++) a[i] = Qs[kk][ty * 4 + i];
#pragma unroll
        for (int j = 0; j < 4; j++) bb[j] = Ks[kk][tx * 4 + j];
#pragma unroll
        for (int i = 0; i < 4; i++)
#pragma unroll
            for (int j = 0; j < 4; j++)
                acc[i][j] = fmaf(a[i], bb[j], acc[i][j]);
    }

#pragma unroll
    for (int i = 0; i < 4; i++) {
        long roff = ((long)z * Tn + (q0 + ty * 4 + i)) * Tn + k0 + tx * 4;
        *(float4*)&scores[roff] = *(float4*)&acc[i][0];
    }
}

// ---------------- masked softmax over each score row (in place) ----------------
__global__ void __launch_bounds__(256) softmax_kernel(float* __restrict__ scores)
{
    long z = blockIdx.x;                 // bh*T + q
    int q  = (int)(z & (Tn - 1));
    int bh = (int)(z >> 10);
    int b  = bh >> 4;
    float* row = scores + z * Tn;
    int kmax = min(q, g_len[b] - 1);     // valid key range [0, kmax]
    int kwr  = q | 63;                   // last key pv_kernel will read

    int t = threadIdx.x;
    __shared__ float red[256];
    float vals[4];
    float lmax = -3.4e38f;
#pragma unroll
    for (int i = 0; i < 4; i++) {
        int k = t + i * 256;
        vals[i] = (k <= kmax) ? row[k] : -3.4e38f;
        lmax = fmaxf(lmax, vals[i]);
    }
    red[t] = lmax; __syncthreads();
    for (int s = 128; s > 0; s >>= 1) {
        if (t < s) red[t] = fmaxf(red[t], red[t + s]);
        __syncthreads();
    }
    float mx = red[0];
    __syncthreads();

    float lsum = 0.0f;
#pragma unroll
    for (int i = 0; i < 4; i++) {
        int k = t + i * 256;
        float e = (k <= kmax) ? expf(vals[i] - mx) : 0.0f;
        vals[i] = e;
        lsum += e;
    }
    red[t] = lsum; __syncthreads();
    for (int s = 128; s > 0; s >>= 1) {
        if (t < s) red[t] += red[t + s];
        __syncthreads();
    }
    float inv = 1.0f / red[0];
#pragma unroll
    for (int i = 0; i < 4; i++) {
        int k = t + i * 256;
        if (k <= kwr) row[k] = vals[i] * inv;
    }
}

// -------- PV: attn[b][q][h*64+d] = sum_k P . V ; emits split-fp16 directly --------
__global__ void __launch_bounds__(256) pv_kernel(const float* __restrict__ qkv,
                                                 const float* __restrict__ p,
                                                 __half* __restrict__ attns)
{
    int z = blockIdx.z, b = z >> 4, hh = z & 15;
    int q0 = blockIdx.y * 64;
    __shared__ float Ps[32][65];
    __shared__ float Vs[32][64];
    int t = threadIdx.x, ty = t >> 4, tx = t & 15;
    const float* vbase = qkv + (long)(b * Tn) * E3n + 2 * En + hh * HDn;
    const float* prow  = p + ((long)z * Tn + q0) * Tn;

    float acc[4][4];
#pragma unroll
    for (int i = 0; i < 4; i++)
#pragma unroll
        for (int j = 0; j < 4; j++) acc[i][j] = 0.0f;

    int kend = min(Tn, q0 + 64);
    for (int kt = 0; kt < kend; kt += 32) {
        for (int i = t; i < 512; i += 256) {
            int row = i >> 3, c4 = (i & 7) * 4;
            float4 pv = *(const float4*)(prow + (long)row * Tn + kt + c4);
            Ps[c4 + 0][row] = pv.x; Ps[c4 + 1][row] = pv.y;
            Ps[c4 + 2][row] = pv.z; Ps[c4 + 3][row] = pv.w;
        }
        for (int i = t; i < 512; i += 256) {
            int row = i >> 4, c4 = (i & 15) * 4;
            float4 vv = *(const float4*)(vbase + (long)(kt + row) * E3n + c4);
            *(float4*)&Vs[row][c4] = vv;
        }
        __syncthreads();
#pragma unroll 8
        for (int kk = 0; kk < 32; kk++) {
            float a[4], bb[4];
#pragma unroll
            for (int i = 0; i < 4; i++) a[i] = Ps[kk][ty * 4 + i];
#pragma unroll
            for (int j = 0; j < 4; j++) bb[j] = Vs[kk][tx * 4 + j];
#pragma unroll
            for (int i = 0; i < 4; i++)
#pragma unroll
                for (int j = 0; j < 4; j++)
                    acc[i][j] = fmaf(a[i], bb[j], acc[i][j]);
        }
        __syncthreads();
    }

#pragma unroll
    for (int i = 0; i < 4; i++) {
        long off = ((long)(b * Tn) + q0 + ty * 4 + i) * (2 * En) + (hh * HDn + tx * 4) * 2;
        __align__(16) __half o[8];
#pragma unroll
        for (int j = 0; j < 4; j++) {
            float v = acc[i][j];
            __half h = __float2half_rn(v);
            o[2 * j] = h; o[2 * j + 1] = __float2half_rn(v - __half2float(h));
        }
        *(uint4*)&attns[off] = *(const uint4*)o;
    }
}

// ---------------- residual add + LayerNorm (optional split-fp16 out) ----------------
__global__ void __launch_bounds__(256) ln_kernel(const float* __restrict__ res,
                                                 const float* __restrict__ y,
                                                 const float* __restrict__ w,
                                                 const float* __restrict__ bb,
                                                 float* __restrict__ out,
                                                 __half* __restrict__ outs)
{
    long r = blockIdx.x;
    int t = threadIdx.x;
    const float* r0 = res + r * En;
    const float* y0 = y + r * En;
    __shared__ float rs[256], rss[256];
    float v[4];
    float s = 0.0f, ss = 0.0f;
#pragma unroll
    for (int i = 0; i < 4; i++) {
        int idx = t + i * 256;
        v[i] = r0[idx] + y0[idx];
        s += v[i];
        ss += v[i] * v[i];
    }
    rs[t] = s; rss[t] = ss; __syncthreads();
    for (int sh = 128; sh > 0; sh >>= 1) {
        if (t < sh) { rs[t] += rs[t + sh]; rss[t] += rss[t + sh]; }
        __syncthreads();
    }
    float mean = rs[0] * (1.0f / En);
    float var  = rss[0] * (1.0f / En) - mean * mean;
    float inv  = rsqrtf(var + LN_EPS);
#pragma unroll
    for (int i = 0; i < 4; i++) {
        int idx = t + i * 256;
        float o = w[idx] * (v[i] - mean) * inv + bb[idx];
        out[r * En + idx] = o;
        if (outs) {
            __half h = __float2half_rn(o);
            __half l = __float2half_rn(o - __half2float(h));
            *(__half2*)(outs + r * (2 * En) + 2 * idx) = __halves2half2(h, l);
        }
    }
}

// ---------------- launch ----------------
static inline void split(const float* src, __half* dst, long n) {
    long n4 = n >> 2;
    split_kernel<<<(unsigned)((n4 + 255) / 256), 256>>>(src, dst, n4);
}

extern "C" void kernel_launch(void* const* d_in, const int* in_sizes, int n_in,
                              void* d_out, int out_size)
{
    const float* x     = (const float*)d_in[0];
    const float* in_w  = (const float*)d_in[1];
    const float* in_b  = (const float*)d_in[2];
    const float* out_w = (const float*)d_in[3];
    const float* out_b = (const float*)d_in[4];
    const float* fc1_w = (const float*)d_in[5];
    const float* fc1_b = (const float*)d_in[6];
    const float* fc2_w = (const float*)d_in[7];
    const float* fc2_b = (const float*)d_in[8];
    const float* ln1_w = (const float*)d_in[9];
    const float* ln1_b = (const float*)d_in[10];
    const float* ln2_w = (const float*)d_in[11];
    const float* ln2_b = (const float*)d_in[12];
    const void*  pad_mask = d_in[13];
    float* out = (float*)d_out;

    float *qkv, *scores, *tmp, *x1;
    cudaGetSymbolAddress((void**)&qkv,    g_qkv);
    cudaGetSymbolAddress((void**)&scores, g_scores);
    cudaGetSymbolAddress((void**)&tmp,    g_tmp);
    cudaGetSymbolAddress((void**)&x1,     g_x1);
    __half *xs, *attns, *x1s, *ffns, *inws, *outws, *fc1ws, *fc2ws;
    cudaGetSymbolAddress((void**)&xs,    g_xs);
    cudaGetSymbolAddress((void**)&attns, g_attns);
    cudaGetSymbolAddress((void**)&x1s,   g_x1s);
    cudaGetSymbolAddress((void**)&ffns,  g_ffns);
    cudaGetSymbolAddress((void**)&inws,  g_inws);
    cudaGetSymbolAddress((void**)&outws, g_outws);
    cudaGetSymbolAddress((void**)&fc1ws, g_fc1ws);
    cudaGetSymbolAddress((void**)&fc2ws, g_fc2ws);

    const int GSMEM = GST * STAGE_BYTES;   // 96 KB
    cudaFuncSetAttribute(gemm_mma<false, false>, cudaFuncAttributeMaxDynamicSharedMemorySize, GSMEM);
    cudaFuncSetAttribute(gemm_mma<true, true>,   cudaFuncAttributeMaxDynamicSharedMemorySize, GSMEM);

    // 0. sequence lengths from padding mask (dtype auto-detected)
    len_kernel<<<1, 256>>>(pad_mask);

    // 1. QKV projection: [8192,1024] x [3072,1024]^T (fp16 hi/lo split, K2=2048)
    split(x, xs, (long)TOK * En);
    split(in_w, inws, (long)E3n * En);
    gemm_mma<false, false><<<dim3(E3n / 128, TOK / 128), 256, GSMEM>>>(xs, inws, in_b, qkv, E3n, 2 * En);

    // 2-4. attention (SIMT fp32); PV emits split-fp16 attn directly
    scores_kernel<<<dim3(Tn / 64, Tn / 64, BHn), 256>>>(qkv, scores);
    softmax_kernel<<<BHn * Tn, 256>>>(scores);
    pv_kernel<<<dim3(1, Tn / 64, BHn), 256>>>(qkv, scores, attns);

    // 5. output projection
    split(out_w, outws, (long)En * En);
    gemm_mma<false, false><<<dim3(En / 128, TOK / 128), 256, GSMEM>>>(attns, outws, out_b, tmp, En, 2 * En);

    // 6. residual + LN1 -> x1 (fp32) + x1s (split fp16)
    ln_kernel<<<TOK, 256>>>(x, tmp, ln1_w, ln1_b, x1, x1s);

    // 7. FC1 + ReLU: [8192,1024] x [4096,1024]^T -> split-fp16 ffns directly
    split(fc1_w, fc1ws, (long)FFn * En);
    gemm_mma<true, true><<<dim3(FFn / 128, TOK / 128), 256, GSMEM>>>(x1s, fc1ws, fc1_b, ffns, FFn, 2 * En);

    // 8. FC2: [8192,4096] x [1024,4096]^T (K2=8192)
    split(fc2_w, fc2ws, (long)En * FFn);
    gemm_mma<false, false><<<dim3(En / 128, TOK / 128), 256, GSMEM>>>(ffns, fc2ws, fc2_b, tmp, En, 2 * FFn);

    // 9. residual + LN2 -> out
    ln_kernel<<<TOK, 256>>>(x1, tmp, ln2_w, ln2_b, out, (half*)nullptr);
}

// round 6
// speedup vs baseline: 4.3070x; 1.3871x over previous
#include <cuda_runtime.h>
#include <cuda_fp16.h>
#include <stdint.h>
#include <math.h>

// Problem constants
#define Bn 8
#define Tn 1024
#define En 1024
#define Hn 16
#define HDn 64
#define FFn 4096
#define E3n 3072
#define TOK 8192          // B*T
#define BHn 128           // B*H
#define SCALE_Q 0.125f    // 64^-0.5
#define LN_EPS 1e-12f

// ======================= PTX helpers (sm_80+ features only) =======================
__device__ __forceinline__ uint32_t smem_u32(const void* p) {
    uint32_t a;
    asm("{ .reg .u64 t; cvta.to.shared.u64 t, %1; cvt.u32.u64 %0, t; }" : "=r"(a) : "l"(p));
    return a;
}
#define CP_ASYNC16(dst, src) \
    asm volatile("cp.async.cg.shared.global [%0], [%1], 16;" :: "r"(dst), "l"(src) : "memory")
#define CP_COMMIT() asm volatile("cp.async.commit_group;" ::: "memory")
#define CP_WAIT2()  asm volatile("cp.async.wait_group 2;" ::: "memory")
#define CP_WAIT1()  asm volatile("cp.async.wait_group 1;" ::: "memory")
#define LDSM_X4(r0, r1, r2, r3, addr) \
    asm volatile("ldmatrix.sync.aligned.m8n8.x4.shared.b16 {%0,%1,%2,%3}, [%4];" \
        : "=r"(r0), "=r"(r1), "=r"(r2), "=r"(r3) : "r"(addr))
#define MMA16816(d, a, b) \
    asm volatile("mma.sync.aligned.m16n8k16.row.col.f32.f16.f16.f32 " \
        "{%0,%1,%2,%3}, {%4,%5,%6,%7}, {%8,%9}, {%0,%1,%2,%3};" \
        : "+f"((d)[0]), "+f"((d)[1]), "+f"((d)[2]), "+f"((d)[3]) \
        : "r"((a)[0]), "r"((a)[1]), "r"((a)[2]), "r"((a)[3]), "r"((b)[0]), "r"((b)[1]))

// ---------------- static scratch (no allocations allowed) ----------------
__device__ float g_scores[(long)BHn * Tn * Tn];        // 512 MB fp32 S
__device__ __half g_p2[(long)BHn * Tn * 2 * Tn];       // 536 MB split-fp16 P
__device__ __half g_qkvs[(long)TOK * 2 * E3n];         // split-fp16 qkv
__device__ __half g_vt2[(long)BHn * HDn * 2 * Tn];     // split-fp16 V^T per head
__device__ float g_tmp[TOK * En];
__device__ float g_x1[TOK * En];
__device__ int   g_len[Bn];
__device__ __half g_xs[(long)TOK * 2 * En];
__device__ __half g_attns[(long)TOK * 2 * En];
__device__ __half g_x1s[(long)TOK * 2 * En];
__device__ __half g_ffns[(long)TOK * 2 * FFn];
__device__ __half g_inws[(long)E3n * 2 * En];
__device__ __half g_outws[(long)En * 2 * En];
__device__ __half g_fc1ws[(long)FFn * 2 * En];
__device__ __half g_fc2ws[(long)En * 2 * FFn];

// ---------------- fp32 -> interleaved fp16 hi/lo split ----------------
__global__ void __launch_bounds__(256) split_kernel(const float* __restrict__ src,
                                                    __half* __restrict__ dst, long n4)
{
    long i = (long)blockIdx.x * 256 + threadIdx.x;
    if (i >= n4) return;
    float4 v = ((const float4*)src)[i];
    __align__(16) __half o[8];
    float a; __half h;
    a = v.x; h = __float2half_rn(a); o[0] = h; o[1] = __float2half_rn(a - __half2float(h));
    a = v.y; h = __float2half_rn(a); o[2] = h; o[3] = __float2half_rn(a - __half2float(h));
    a = v.z; h = __float2half_rn(a); o[4] = h; o[5] = __float2half_rn(a - __half2float(h));
    a = v.w; h = __float2half_rn(a); o[6] = h; o[7] = __float2half_rn(a - __half2float(h));
    ((uint4*)dst)[i] = *(const uint4*)o;
}

// ---------------- mask dtype detection + lengths ----------------
__global__ void len_kernel(const void* maskp) {
    __shared__ int s_kind;   // 0=i32, 1=u8, 2=f32
    __shared__ int s_len[Bn];
    int t = threadIdx.x;
    if (t == 0) s_kind = 0;
    if (t < Bn) s_len[t] = Tn;
    __syncthreads();
    const unsigned int* w = (const unsigned int*)maskp;
    for (int i = t; i < 2048; i += blockDim.x) {
        unsigned int v = w[i];
        if (v == 0x3F800000u) atomicMax(&s_kind, 2);
        else if (v > 1u)      atomicMax(&s_kind, 1);
    }
    __syncthreads();
    int kind = s_kind;
    const unsigned char* mb = (const unsigned char*)maskp;
    const int* mi = (const int*)maskp;
    const float* mf = (const float*)maskp;
    for (int i = t; i < Bn * Tn; i += blockDim.x) {
        int b = i >> 10, tt = i & (Tn - 1);
        int m;
        if (kind == 1)      m = (int)mb[i];
        else if (kind == 2) m = (mf[i] != 0.0f);
        else                m = mi[i];
        if (m) atomicMin(&s_len[b], tt);
    }
    __syncthreads();
    if (t < Bn) g_len[t] = s_len[t];
}

// ============ mma.sync GEMM (proven R4): C = A2[M,K2] * B2[N,K2]^T + bias ============
#define GST 3
#define STAGE_BYTES 32768

template<bool RELU, bool SPLIT_OUT>
__global__ void __launch_bounds__(256) gemm_mma(
    const __half* __restrict__ A2,
    const __half* __restrict__ B2,
    const float* __restrict__ bias,
    void* __restrict__ Cv, int N, int K2)
{
    extern __shared__ char smem[];
    uint32_t sb = smem_u32(smem);
    int tid = threadIdx.x, lane = tid & 31, w = tid >> 5;
    int m0 = blockIdx.y * 128, n0 = blockIdx.x * 128;
    int warpM = (w >> 2) * 64, warpN = (w & 3) * 32;
    const int CH = K2 >> 6;

    auto issue = [&](int c) {
        if (c < CH) {
            uint32_t base = sb + (c % GST) * STAGE_BYTES;
            long kb = (long)c * 64;
#pragma unroll
            for (int i = 0; i < 4; i++) {
                int flat = i * 256 + tid;
                int row = flat >> 3;
                int seg = flat & 7;
                uint32_t off = (uint32_t)(row * 128 + ((seg * 16) ^ ((row & 7) * 16)));
                CP_ASYNC16(base + off,         A2 + (long)(m0 + row) * K2 + kb + seg * 8);
                CP_ASYNC16(base + 16384 + off, B2 + (long)(n0 + row) * K2 + kb + seg * 8);
            }
        }
        CP_COMMIT();
    };
    issue(0); issue(1); issue(2);

    float acc[4][4][4];
#pragma unroll
    for (int i = 0; i < 4; i++)
#pragma unroll
        for (int j = 0; j < 4; j++)
#pragma unroll
            for (int k = 0; k < 4; k++) acc[i][j][k] = 0.0f;

    int mrow = warpM + (lane & 7) + ((lane >> 3) & 1) * 8;
    int acol = (lane >> 4) * 16;
    int nrow = warpN + (lane & 7) + ((lane >> 4) & 1) * 8;
    int bcol = ((lane >> 3) & 1) * 16;

    for (int c = 0; c < CH; c++) {
        CP_WAIT2();
        __syncthreads();
        uint32_t sA = sb + (c % GST) * STAGE_BYTES;
        uint32_t sB = sA + 16384;
#pragma unroll
        for (int ks = 0; ks < 4; ks++) {
            uint32_t af[4][4];
#pragma unroll
            for (int mi = 0; mi < 4; mi++) {
                int m = mrow + mi * 16;
                uint32_t addr = sA + m * 128 + ((ks * 32 + acol) ^ ((m & 7) * 16));
                LDSM_X4(af[mi][0], af[mi][1], af[mi][2], af[mi][3], addr);
            }
            uint32_t bf[4][2];
#pragma unroll
            for (int nb = 0; nb < 2; nb++) {
                int n = nrow + nb * 16;
                uint32_t addr = sB + n * 128 + ((ks * 32 + bcol) ^ ((n & 7) * 16));
                uint32_t r0, r1, r2, r3;
                LDSM_X4(r0, r1, r2, r3, addr);
                bf[nb * 2][0] = r0;     bf[nb * 2][1] = r1;
                bf[nb * 2 + 1][0] = r2; bf[nb * 2 + 1][1] = r3;
            }
#pragma unroll
            for (int mi = 0; mi < 4; mi++)
#pragma unroll
                for (int ni = 0; ni < 4; ni++)
                    MMA16816(acc[mi][ni], af[mi], bf[ni]);
        }
        __syncthreads();
        issue(c + 3);
    }

#pragma unroll
    for (int mi = 0; mi < 4; mi++) {
        int r = m0 + warpM + mi * 16 + (lane >> 2);
#pragma unroll
        for (int ni = 0; ni < 4; ni++) {
            int col = n0 + warpN + ni * 8 + (lane & 3) * 2;
            float b0 = bias[col], b1 = bias[col + 1];
            float v0 = acc[mi][ni][0] + b0, v1 = acc[mi][ni][1] + b1;
            float v2 = acc[mi][ni][2] + b0, v3 = acc[mi][ni][3] + b1;
            if (RELU) {
                v0 = fmaxf(v0, 0.0f); v1 = fmaxf(v1, 0.0f);
                v2 = fmaxf(v2, 0.0f); v3 = fmaxf(v3, 0.0f);
            }
            if (SPLIT_OUT) {
                __half* C = (__half*)Cv;
                __align__(8) __half o[4];
                __half h;
                h = __float2half_rn(v0); o[0] = h; o[1] = __float2half_rn(v0 - __half2float(h));
                h = __float2half_rn(v1); o[2] = h; o[3] = __float2half_rn(v1 - __half2float(h));
                *(uint2*)(C + (long)r * (2 * N) + 2 * col) = *(const uint2*)o;
                h = __float2half_rn(v2); o[0] = h; o[1] = __float2half_rn(v2 - __half2float(h));
                h = __float2half_rn(v3); o[2] = h; o[3] = __float2half_rn(v3 - __half2float(h));
                *(uint2*)(C + (long)(r + 8) * (2 * N) + 2 * col) = *(const uint2*)o;
            } else {
                float* C = (float*)Cv;
                float2 p0; p0.x = v0; p0.y = v1;
                float2 p1; p1.x = v2; p1.y = v3;
                *(float2*)(C + (long)r * N + col) = p0;
                *(float2*)(C + (long)(r + 8) * N + col) = p1;
            }
        }
    }
}

// ---------------- shared tile loader: 64 rows x 256B, swizzled ----------------
__device__ __forceinline__ void load_tile64x256(uint32_t dst, const __half* src,
                                                long strideHalfs, int tid)
{
#pragma unroll
    for (int i = 0; i < 4; i++) {
        int flat = i * 256 + tid;
        int row = flat >> 4;
        int seg = flat & 15;
        uint32_t off = (uint32_t)(row * 256 + ((seg * 16) ^ ((row & 7) * 16)));
        CP_ASYNC16(dst + off, src + (long)row * strideHalfs + seg * 8);
    }
}

// ============ scores: S[bh][q][k] = (Q2 . K2) * SCALE via mma, causal tiles ============
__global__ void __launch_bounds__(256) scores_mma(const __half* __restrict__ qkv2,
                                                  float* __restrict__ scores)
{
    int qt = blockIdx.x, bh = blockIdx.y;
    int b = bh >> 4, h = bh & 15;
    int q0 = qt * 64;
    extern __shared__ char smem[];
    uint32_t sQ = smem_u32(smem);
    uint32_t sKb = sQ + 16384;
    int tid = threadIdx.x, lane = tid & 31, w = tid >> 5;
    int warpM = (w >> 1) * 16, warpN = (w & 1) * 32;

    const __half* qbase = qkv2 + (long)(b * Tn + q0) * 6144 + 128 * h;
    const __half* kbase = qkv2 + (long)(b * Tn) * 6144 + 2048 + 128 * h;

    load_tile64x256(sQ, qbase, 6144, tid);
    load_tile64x256(sKb, kbase, 6144, tid);
    CP_COMMIT();
    if (qt >= 1) load_tile64x256(sKb + 16384, kbase + (long)64 * 6144, 6144, tid);
    CP_COMMIT();

    int mrow = warpM + (lane & 7) + ((lane >> 3) & 1) * 8;
    int acol = (lane >> 4) * 16;
    int nrow0 = warpN + (lane & 7) + ((lane >> 4) & 1) * 8;
    int bcol = ((lane >> 3) & 1) * 16;

    for (int kt = 0; kt <= qt; kt++) {
        CP_WAIT1();
        __syncthreads();
        uint32_t sK = sKb + (kt & 1) * 16384;
        float c[4][4];
#pragma unroll
        for (int i = 0; i < 4; i++)
#pragma unroll
            for (int j = 0; j < 4; j++) c[i][j] = 0.0f;
#pragma unroll
        for (int ks = 0; ks < 8; ks++) {
            uint32_t af[4];
            {
                int m = mrow;
                uint32_t addr = sQ + m * 256 + ((ks * 32 + acol) ^ ((m & 7) * 16));
                LDSM_X4(af[0], af[1], af[2], af[3], addr);
            }
            uint32_t bf[4][2];
#pragma unroll
            for (int nb = 0; nb < 2; nb++) {
                int n = nrow0 + nb * 16;
                uint32_t addr = sK + n * 256 + ((ks * 32 + bcol) ^ ((n & 7) * 16));
                uint32_t r0, r1, r2, r3;
                LDSM_X4(r0, r1, r2, r3, addr);
                bf[nb * 2][0] = r0;     bf[nb * 2][1] = r1;
                bf[nb * 2 + 1][0] = r2; bf[nb * 2 + 1][1] = r3;
            }
#pragma unroll
            for (int ni = 0; ni < 4; ni++)
                MMA16816(c[ni], af, bf[ni]);
        }
        {
            int q = q0 + warpM + (lane >> 2);
            long ro = ((long)bh * Tn + q) * Tn + kt * 64;
#pragma unroll
            for (int ni = 0; ni < 4; ni++) {
                int col = warpN + ni * 8 + (lane & 3) * 2;
                float2 p0; p0.x = c[ni][0] * SCALE_Q; p0.y = c[ni][1] * SCALE_Q;
                float2 p1; p1.x = c[ni][2] * SCALE_Q; p1.y = c[ni][3] * SCALE_Q;
                *(float2*)(scores + ro + col) = p0;
                *(float2*)(scores + ro + 8 * Tn + col) = p1;
            }
        }
        __syncthreads();
        if (kt + 2 <= qt)
            load_tile64x256(sKb + (kt & 1) * 16384, kbase + (long)(kt + 2) * 64 * 6144, 6144, tid);
        CP_COMMIT();
    }
}

// ---------- warp-per-row masked softmax: fp32 scores -> split-fp16 P ----------
__global__ void __launch_bounds__(256) softmax_warp(const float* __restrict__ scores,
                                                    __half* __restrict__ p2)
{
    int wz = blockIdx.x * 8 + (threadIdx.x >> 5);
    int lane = threadIdx.x & 31;
    int q = wz & (Tn - 1);
    int bh = wz >> 10;
    int b = bh >> 4;
    const float* row = scores + (long)wz * Tn;
    int kmax = min(q, g_len[b] - 1);
    int kwr = q | 63;

    float4 vals[8];
    float mx = -3.4e38f;
#pragma unroll
    for (int c = 0; c < 8; c++) {
        int k4 = c * 128 + lane * 4;
        float4 f;
        if (k4 <= kmax) f = *(const float4*)(row + k4);
        else f.x = f.y = f.z = f.w = -3.4e38f;
        if (k4 + 1 > kmax) f.y = -3.4e38f;
        if (k4 + 2 > kmax) f.z = -3.4e38f;
        if (k4 + 3 > kmax) f.w = -3.4e38f;
        vals[c] = f;
        mx = fmaxf(mx, fmaxf(fmaxf(f.x, f.y), fmaxf(f.z, f.w)));
    }
#pragma unroll
    for (int s = 16; s > 0; s >>= 1)
        mx = fmaxf(mx, __shfl_xor_sync(0xFFFFFFFFu, mx, s));

    float sum = 0.0f;
#pragma unroll
    for (int c = 0; c < 8; c++) {
        float4 f = vals[c];
        f.x = (f.x > -3.0e38f) ? expf(f.x - mx) : 0.0f;
        f.y = (f.y > -3.0e38f) ? expf(f.y - mx) : 0.0f;
        f.z = (f.z > -3.0e38f) ? expf(f.z - mx) : 0.0f;
        f.w = (f.w > -3.0e38f) ? expf(f.w - mx) : 0.0f;
        vals[c] = f;
        sum += f.x + f.y + f.z + f.w;
    }
#pragma unroll
    for (int s = 16; s > 0; s >>= 1)
        sum += __shfl_xor_sync(0xFFFFFFFFu, sum, s);
    float inv = 1.0f / sum;

    __half* prow = p2 + (long)wz * (2 * Tn);
#pragma unroll
    for (int c = 0; c < 8; c++) {
        int k4 = c * 128 + lane * 4;
        if (k4 > kwr) continue;
        float4 f = vals[c];
        __align__(16) __half o[8];
        float p; __half hh;
        p = f.x * inv; hh = __float2half_rn(p); o[0] = hh; o[1] = __float2half_rn(p - __half2float(hh));
        p = f.y * inv; hh = __float2half_rn(p); o[2] = hh; o[3] = __float2half_rn(p - __half2float(hh));
        p = f.z * inv; hh = __float2half_rn(p); o[4] = hh; o[5] = __float2half_rn(p - __half2float(hh));
        p = f.w * inv; hh = __float2half_rn(p); o[6] = hh; o[7] = __float2half_rn(p - __half2float(hh));
        *(uint4*)(prow + 2 * k4) = *(const uint4*)o;
    }
}

// ---------- build split V^T: vt2[bh][d][2k] from split qkv2 ----------
__global__ void __launch_bounds__(256) vt_kernel(const __half* __restrict__ qkv2,
                                                 __half* __restrict__ vt2)
{
    int kt = blockIdx.x, bh = blockIdx.y;
    int b = bh >> 4, h = bh & 15;
    __shared__ float Vs[64][65];
    int tid = threadIdx.x;
    const __half* vbase = qkv2 + (long)(b * Tn + kt * 64) * 6144 + 4096 + 128 * h;
    // read 64 rows x 128 halfs (h/l pairs = 64 d-values), recombine to fp32
    for (int i = tid; i < 1024; i += 256) {
        int r = i >> 4, seg = i & 15;           // 16 x uint4 per row
        uint4 u = *(const uint4*)(vbase + (long)r * 6144 + seg * 8);
        const __half* hp = (const __half*)&u;
#pragma unroll
        for (int j = 0; j < 4; j++)
            Vs[r][seg * 4 + j] = __half2float(hp[2 * j]) + __half2float(hp[2 * j + 1]);
    }
    __syncthreads();
    for (int i = tid; i < 4096; i += 256) {
        int d = i >> 6, k = i & 63;
        float v = Vs[k][d];
        __half hh = __float2half_rn(v);
        __half ll = __float2half_rn(v - __half2float(hh));
        *(__half2*)(vt2 + ((long)(bh * 64 + d)) * (2 * Tn) + 2 * (kt * 64 + k)) =
            __halves2half2(hh, ll);
    }
}

// ============ PV: O[q][d] = sum_k P . V via mma, accumulate across causal tiles ============
__global__ void __launch_bounds__(256) pv_mma(const __half* __restrict__ p2,
                                              const __half* __restrict__ vt2,
                                              __half* __restrict__ attns)
{
    int qt = blockIdx.x, bh = blockIdx.y;
    int b = bh >> 4, h = bh & 15;
    int q0 = qt * 64;
    extern __shared__ char smem[];
    uint32_t s0 = smem_u32(smem);
    int tid = threadIdx.x, lane = tid & 31, w = tid >> 5;
    int warpM = (w >> 1) * 16, warpN = (w & 1) * 32;

    const __half* pbase = p2 + (long)(bh * Tn + q0) * (2 * Tn);
    const __half* vbase = vt2 + (long)(bh * 64) * (2 * Tn);

    load_tile64x256(s0, pbase, 2 * Tn, tid);
    load_tile64x256(s0 + 16384, vbase, 2 * Tn, tid);
    CP_COMMIT();
    if (qt >= 1) {
        load_tile64x256(s0 + 32768, pbase + 128, 2 * Tn, tid);
        load_tile64x256(s0 + 49152, vbase + 128, 2 * Tn, tid);
    }
    CP_COMMIT();

    int mrow = warpM + (lane & 7) + ((lane >> 3) & 1) * 8;
    int acol = (lane >> 4) * 16;
    int nrow0 = warpN + (lane & 7) + ((lane >> 4) & 1) * 8;
    int bcol = ((lane >> 3) & 1) * 16;

    float c[4][4];
#pragma unroll
    for (int i = 0; i < 4; i++)
#pragma unroll
        for (int j = 0; j < 4; j++) c[i][j] = 0.0f;

    for (int kt = 0; kt <= qt; kt++) {
        CP_WAIT1();
        __syncthreads();
        uint32_t sP = s0 + (kt & 1) * 32768;
        uint32_t sV = sP + 16384;
#pragma unroll
        for (int ks = 0; ks < 8; ks++) {
            uint32_t af[4];
            {
                int m = mrow;
                uint32_t addr = sP + m * 256 + ((ks * 32 + acol) ^ ((m & 7) * 16));
                LDSM_X4(af[0], af[1], af[2], af[3], addr);
            }
            uint32_t bf[4][2];
#pragma unroll
            for (int nb = 0; nb < 2; nb++) {
                int n = nrow0 + nb * 16;
                uint32_t addr = sV + n * 256 + ((ks * 32 + bcol) ^ ((n & 7) * 16));
                uint32_t r0, r1, r2, r3;
                LDSM_X4(r0, r1, r2, r3, addr);
                bf[nb * 2][0] = r0;     bf[nb * 2][1] = r1;
                bf[nb * 2 + 1][0] = r2; bf[nb * 2 + 1][1] = r3;
            }
#pragma unroll
            for (int ni = 0; ni < 4; ni++)
                MMA16816(c[ni], af, bf[ni]);
        }
        __syncthreads();
        if (kt + 2 <= qt) {
            uint32_t dst = s0 + (kt & 1) * 32768;
            load_tile64x256(dst, pbase + (long)(kt + 2) * 128, 2 * Tn, tid);
            load_tile64x256(dst + 16384, vbase + (long)(kt + 2) * 128, 2 * Tn, tid);
        }
        CP_COMMIT();
    }

    // epilogue: split-fp16 attn
    int q = q0 + warpM + (lane >> 2);
    long tok = (long)b * Tn + q;
#pragma unroll
    for (int ni = 0; ni < 4; ni++) {
        int gcol = h * 64 + warpN + ni * 8 + (lane & 3) * 2;
        __align__(8) __half o[4];
        __half hh;
        float v0 = c[ni][0], v1 = c[ni][1], v2 = c[ni][2], v3 = c[ni][3];
        hh = __float2half_rn(v0); o[0] = hh; o[1] = __float2half_rn(v0 - __half2float(hh));
        hh = __float2half_rn(v1); o[2] = hh; o[3] = __float2half_rn(v1 - __half2float(hh));
        *(uint2*)(attns + tok * (2 * En) + 2 * gcol) = *(const uint2*)o;
        hh = __float2half_rn(v2); o[0] = hh; o[1] = __float2half_rn(v2 - __half2float(hh));
        hh = __float2half_rn(v3); o[2] = hh; o[3] = __float2half_rn(v3 - __half2float(hh));
        *(uint2*)(attns + (tok + 8) * (2 * En) + 2 * gcol) = *(const uint2*)o;
    }
}

// ---------------- residual add + LayerNorm (optional split-fp16 out) ----------------
__global__ void __launch_bounds__(256) ln_kernel(const float* __restrict__ res,
                                                 const float* __restrict__ y,
                                                 const float* __restrict__ w,
                                                 const float* __restrict__ bb,
                                                 float* __restrict__ out,
                                                 __half* __restrict__ outs)
{
    long r = blockIdx.x;
    int t = threadIdx.x;
    const float* r0 = res + r * En;
    const float* y0 = y + r * En;
    __shared__ float rs[256], rss[256];
    float v[4];
    float s = 0.0f, ss = 0.0f;
#pragma unroll
    for (int i = 0; i < 4; i++) {
        int idx = t + i * 256;
        v[i] = r0[idx] + y0[idx];
        s += v[i];
        ss += v[i] * v[i];
    }
    rs[t] = s; rss[t] = ss; __syncthreads();
    for (int sh = 128; sh > 0; sh >>= 1) {
        if (t < sh) { rs[t] += rs[t + sh]; rss[t] += rss[t + sh]; }
        __syncthreads();
    }
    float mean = rs[0] * (1.0f / En);
    float var  = rss[0] * (1.0f / En) - mean * mean;
    float inv  = rsqrtf(var + LN_EPS);
#pragma unroll
    for (int i = 0; i < 4; i++) {
        int idx = t + i * 256;
        float o = w[idx] * (v[i] - mean) * inv + bb[idx];
        out[r * En + idx] = o;
        if (outs) {
            __half h = __float2half_rn(o);
            __half l = __float2half_rn(o - __half2float(h));
            *(__half2*)(outs + r * (2 * En) + 2 * idx) = __halves2half2(h, l);
        }
    }
}

// ---------------- launch ----------------
static inline void split(const float* src, __half* dst, long n) {
    long n4 = n >> 2;
    split_kernel<<<(unsigned)((n4 + 255) / 256), 256>>>(src, dst, n4);
}

extern "C" void kernel_launch(void* const* d_in, const int* in_sizes, int n_in,
                              void* d_out, int out_size)
{
    const float* x     = (const float*)d_in[0];
    const float* in_w  = (const float*)d_in[1];
    const float* in_b  = (const float*)d_in[2];
    const float* out_w = (const float*)d_in[3];
    const float* out_b = (const float*)d_in[4];
    const float* fc1_w = (const float*)d_in[5];
    const float* fc1_b = (const float*)d_in[6];
    const float* fc2_w = (const float*)d_in[7];
    const float* fc2_b = (const float*)d_in[8];
    const float* ln1_w = (const float*)d_in[9];
    const float* ln1_b = (const float*)d_in[10];
    const float* ln2_w = (const float*)d_in[11];
    const float* ln2_b = (const float*)d_in[12];
    const void*  pad_mask = d_in[13];
    float* out = (float*)d_out;

    float *scores, *tmp, *x1;
    cudaGetSymbolAddress((void**)&scores, g_scores);
    cudaGetSymbolAddress((void**)&tmp,    g_tmp);
    cudaGetSymbolAddress((void**)&x1,     g_x1);
    __half *qkvs, *p2, *vt2, *xs, *attns, *x1s, *ffns, *inws, *outws, *fc1ws, *fc2ws;
    cudaGetSymbolAddress((void**)&qkvs,  g_qkvs);
    cudaGetSymbolAddress((void**)&p2,    g_p2);
    cudaGetSymbolAddress((void**)&vt2,   g_vt2);
    cudaGetSymbolAddress((void**)&xs,    g_xs);
    cudaGetSymbolAddress((void**)&attns, g_attns);
    cudaGetSymbolAddress((void**)&x1s,   g_x1s);
    cudaGetSymbolAddress((void**)&ffns,  g_ffns);
    cudaGetSymbolAddress((void**)&inws,  g_inws);
    cudaGetSymbolAddress((void**)&outws, g_outws);
    cudaGetSymbolAddress((void**)&fc1ws, g_fc1ws);
    cudaGetSymbolAddress((void**)&fc2ws, g_fc2ws);

    const int GSMEM = GST * STAGE_BYTES;   // 96 KB
    cudaFuncSetAttribute(gemm_mma<false, false>, cudaFuncAttributeMaxDynamicSharedMemorySize, GSMEM);
    cudaFuncSetAttribute(gemm_mma<false, true>,  cudaFuncAttributeMaxDynamicSharedMemorySize, GSMEM);
    cudaFuncSetAttribute(gemm_mma<true, true>,   cudaFuncAttributeMaxDynamicSharedMemorySize, GSMEM);
    cudaFuncSetAttribute(scores_mma, cudaFuncAttributeMaxDynamicSharedMemorySize, 49152);
    cudaFuncSetAttribute(pv_mma,     cudaFuncAttributeMaxDynamicSharedMemorySize, 65536);

    // 0. sequence lengths
    len_kernel<<<1, 256>>>(pad_mask);

    // 1. QKV projection -> split-fp16 qkvs directly
    split(x, xs, (long)TOK * En);
    split(in_w, inws, (long)E3n * En);
    gemm_mma<false, true><<<dim3(E3n / 128, TOK / 128), 256, GSMEM>>>(xs, inws, in_b, qkvs, E3n, 2 * En);

    // 2. attention: tensor-core scores, warp softmax, tensor-core PV
    vt_kernel<<<dim3(Tn / 64, BHn), 256>>>(qkvs, vt2);
    scores_mma<<<dim3(Tn / 64, BHn), 256, 49152>>>(qkvs, scores);
    softmax_warp<<<BHn * Tn / 8, 256>>>(scores, p2);
    pv_mma<<<dim3(Tn / 64, BHn), 256, 65536>>>(p2, vt2, attns);

    // 3. output projection
    split(out_w, outws, (long)En * En);
    gemm_mma<false, false><<<dim3(En / 128, TOK / 128), 256, GSMEM>>>(attns, outws, out_b, tmp, En, 2 * En);

    // 4. residual + LN1
    ln_kernel<<<TOK, 256>>>(x, tmp, ln1_w, ln1_b, x1, x1s);

    // 5. FC1 + ReLU -> split-fp16 ffns
    split(fc1_w, fc1ws, (long)FFn * En);
    gemm_mma<true, true><<<dim3(FFn / 128, TOK / 128), 256, GSMEM>>>(x1s, fc1ws, fc1_b, ffns, FFn, 2 * En);

    // 6. FC2
    split(fc2_w, fc2ws, (long)En * FFn);
    gemm_mma<false, false><<<dim3(En / 128, TOK / 128), 256, GSMEM>>>(ffns, fc2ws, fc2_b, tmp, En, 2 * FFn);

    // 7. residual + LN2 -> out
    ln_kernel<<<TOK, 256>>>(x1, tmp, ln2_w, ln2_b, out, (half*)nullptr);
}

// round 7
// speedup vs baseline: 7.2633x; 1.6864x over previous
#include <cuda_runtime.h>
#include <cuda_fp16.h>
#include <stdint.h>
#include <math.h>

// Problem constants
#define Bn 8
#define Tn 1024
#define En 1024
#define Hn 16
#define HDn 64
#define FFn 4096
#define E3n 3072
#define TOK 8192          // B*T
#define BHn 128           // B*H
#define SCALE_Q 0.125f    // 64^-0.5
#define LN_EPS 1e-12f

// ======================= PTX helpers (sm_80+ features only) =======================
__device__ __forceinline__ uint32_t smem_u32(const void* p) {
    uint32_t a;
    asm("{ .reg .u64 t; cvta.to.shared.u64 t, %1; cvt.u32.u64 %0, t; }" : "=r"(a) : "l"(p));
    return a;
}
#define CP_ASYNC16(dst, src) \
    asm volatile("cp.async.cg.shared.global [%0], [%1], 16;" :: "r"(dst), "l"(src) : "memory")
#define CP_COMMIT() asm volatile("cp.async.commit_group;" ::: "memory")
#define CP_WAIT2()  asm volatile("cp.async.wait_group 2;" ::: "memory")
#define CP_WAIT1()  asm volatile("cp.async.wait_group 1;" ::: "memory")
#define LDSM_X4(r0, r1, r2, r3, addr) \
    asm volatile("ldmatrix.sync.aligned.m8n8.x4.shared.b16 {%0,%1,%2,%3}, [%4];" \
        : "=r"(r0), "=r"(r1), "=r"(r2), "=r"(r3) : "r"(addr))
#define MMA16816(d, a, b) \
    asm volatile("mma.sync.aligned.m16n8k16.row.col.f32.f16.f16.f32 " \
        "{%0,%1,%2,%3}, {%4,%5,%6,%7}, {%8,%9}, {%0,%1,%2,%3};" \
        : "+f"((d)[0]), "+f"((d)[1]), "+f"((d)[2]), "+f"((d)[3]) \
        : "r"((a)[0]), "r"((a)[1]), "r"((a)[2]), "r"((a)[3]), "r"((b)[0]), "r"((b)[1]))

// ---------------- static scratch (no allocations allowed) ----------------
__device__ float g_scores[(long)BHn * Tn * Tn];        // 512 MB fp32 S
__device__ __half g_ph[(long)BHn * Tn * Tn];           // 268 MB fp16 P
__device__ __half g_qkvh[(long)TOK * E3n];             // fp16 qkv
__device__ __half g_vth[(long)BHn * HDn * Tn];         // fp16 V^T per head
__device__ float g_tmp[TOK * En];
__device__ float g_x1[TOK * En];
__device__ int   g_len[Bn];
__device__ __half g_xh[(long)TOK * En];
__device__ __half g_attnh[(long)TOK * En];
__device__ __half g_x1h[(long)TOK * En];
__device__ __half g_ffnh[(long)TOK * FFn];
__device__ __half g_inwh[(long)E3n * En];
__device__ __half g_outwh[(long)En * En];
__device__ __half g_fc1wh[(long)FFn * En];
__device__ __half g_fc2wh[(long)En * FFn];

// ---------------- fp32 -> fp16 convert ----------------
__global__ void __launch_bounds__(256) cvt_kernel(const float* __restrict__ src,
                                                  __half* __restrict__ dst, long n4)
{
    long i = (long)blockIdx.x * 256 + threadIdx.x;
    if (i >= n4) return;
    float4 v = ((const float4*)src)[i];
    __align__(8) __half o[4];
    o[0] = __float2half_rn(v.x); o[1] = __float2half_rn(v.y);
    o[2] = __float2half_rn(v.z); o[3] = __float2half_rn(v.w);
    ((uint2*)dst)[i] = *(const uint2*)o;
}

// ---------------- mask dtype detection + lengths ----------------
__global__ void len_kernel(const void* maskp) {
    __shared__ int s_kind;   // 0=i32, 1=u8, 2=f32
    __shared__ int s_len[Bn];
    int t = threadIdx.x;
    if (t == 0) s_kind = 0;
    if (t < Bn) s_len[t] = Tn;
    __syncthreads();
    const unsigned int* w = (const unsigned int*)maskp;
    for (int i = t; i < 2048; i += blockDim.x) {
        unsigned int v = w[i];
        if (v == 0x3F800000u) atomicMax(&s_kind, 2);
        else if (v > 1u)      atomicMax(&s_kind, 1);
    }
    __syncthreads();
    int kind = s_kind;
    const unsigned char* mb = (const unsigned char*)maskp;
    const int* mi = (const int*)maskp;
    const float* mf = (const float*)maskp;
    for (int i = t; i < Bn * Tn; i += blockDim.x) {
        int b = i >> 10, tt = i & (Tn - 1);
        int m;
        if (kind == 1)      m = (int)mb[i];
        else if (kind == 2) m = (mf[i] != 0.0f);
        else                m = mi[i];
        if (m) atomicMin(&s_len[b], tt);
    }
    __syncthreads();
    if (t < Bn) g_len[t] = s_len[t];
}

// ============ mma.sync GEMM: C[M,N] = A[M,K](fp16) * B[N,K](fp16)^T + bias ============
#define GST 3
#define STAGE_BYTES 32768

template<bool RELU, bool HALF_OUT>
__global__ void __launch_bounds__(256) gemm_mma(
    const __half* __restrict__ A2,
    const __half* __restrict__ B2,
    const float* __restrict__ bias,
    void* __restrict__ Cv, int N, int K2)
{
    extern __shared__ char smem[];
    uint32_t sb = smem_u32(smem);
    int tid = threadIdx.x, lane = tid & 31, w = tid >> 5;
    int m0 = blockIdx.y * 128, n0 = blockIdx.x * 128;
    int warpM = (w >> 2) * 64, warpN = (w & 3) * 32;
    const int CH = K2 >> 6;

    auto issue = [&](int c) {
        if (c < CH) {
            uint32_t base = sb + (c % GST) * STAGE_BYTES;
            long kb = (long)c * 64;
#pragma unroll
            for (int i = 0; i < 4; i++) {
                int flat = i * 256 + tid;
                int row = flat >> 3;
                int seg = flat & 7;
                uint32_t off = (uint32_t)(row * 128 + ((seg * 16) ^ ((row & 7) * 16)));
                CP_ASYNC16(base + off,         A2 + (long)(m0 + row) * K2 + kb + seg * 8);
                CP_ASYNC16(base + 16384 + off, B2 + (long)(n0 + row) * K2 + kb + seg * 8);
            }
        }
        CP_COMMIT();
    };
    issue(0); issue(1); issue(2);

    float acc[4][4][4];
#pragma unroll
    for (int i = 0; i < 4; i++)
#pragma unroll
        for (int j = 0; j < 4; j++)
#pragma unroll
            for (int k = 0; k < 4; k++) acc[i][j][k] = 0.0f;

    int mrow = warpM + (lane & 7) + ((lane >> 3) & 1) * 8;
    int acol = (lane >> 4) * 16;
    int nrow = warpN + (lane & 7) + ((lane >> 4) & 1) * 8;
    int bcol = ((lane >> 3) & 1) * 16;

    for (int c = 0; c < CH; c++) {
        CP_WAIT2();
        __syncthreads();
        uint32_t sA = sb + (c % GST) * STAGE_BYTES;
        uint32_t sB = sA + 16384;
#pragma unroll
        for (int ks = 0; ks < 4; ks++) {
            uint32_t af[4][4];
#pragma unroll
            for (int mi = 0; mi < 4; mi++) {
                int m = mrow + mi * 16;
                uint32_t addr = sA + m * 128 + ((ks * 32 + acol) ^ ((m & 7) * 16));
                LDSM_X4(af[mi][0], af[mi][1], af[mi][2], af[mi][3], addr);
            }
            uint32_t bf[4][2];
#pragma unroll
            for (int nb = 0; nb < 2; nb++) {
                int n = nrow + nb * 16;
                uint32_t addr = sB + n * 128 + ((ks * 32 + bcol) ^ ((n & 7) * 16));
                uint32_t r0, r1, r2, r3;
                LDSM_X4(r0, r1, r2, r3, addr);
                bf[nb * 2][0] = r0;     bf[nb * 2][1] = r1;
                bf[nb * 2 + 1][0] = r2; bf[nb * 2 + 1][1] = r3;
            }
#pragma unroll
            for (int mi = 0; mi < 4; mi++)
#pragma unroll
                for (int ni = 0; ni < 4; ni++)
                    MMA16816(acc[mi][ni], af[mi], bf[ni]);
        }
        __syncthreads();
        issue(c + 3);
    }

#pragma unroll
    for (int mi = 0; mi < 4; mi++) {
        int r = m0 + warpM + mi * 16 + (lane >> 2);
#pragma unroll
        for (int ni = 0; ni < 4; ni++) {
            int col = n0 + warpN + ni * 8 + (lane & 3) * 2;
            float b0 = bias[col], b1 = bias[col + 1];
            float v0 = acc[mi][ni][0] + b0, v1 = acc[mi][ni][1] + b1;
            float v2 = acc[mi][ni][2] + b0, v3 = acc[mi][ni][3] + b1;
            if (RELU) {
                v0 = fmaxf(v0, 0.0f); v1 = fmaxf(v1, 0.0f);
                v2 = fmaxf(v2, 0.0f); v3 = fmaxf(v3, 0.0f);
            }
            if (HALF_OUT) {
                __half* C = (__half*)Cv;
                __align__(4) __half o[2];
                o[0] = __float2half_rn(v0); o[1] = __float2half_rn(v1);
                *(uint32_t*)(C + (long)r * N + col) = *(const uint32_t*)o;
                o[0] = __float2half_rn(v2); o[1] = __float2half_rn(v3);
                *(uint32_t*)(C + (long)(r + 8) * N + col) = *(const uint32_t*)o;
            } else {
                float* C = (float*)Cv;
                float2 p0; p0.x = v0; p0.y = v1;
                float2 p1; p1.x = v2; p1.y = v3;
                *(float2*)(C + (long)r * N + col) = p0;
                *(float2*)(C + (long)(r + 8) * N + col) = p1;
            }
        }
    }
}

// ---------------- shared tile loader: 64 rows x 128B, swizzled ----------------
__device__ __forceinline__ void load_tile64x128(uint32_t dst, const __half* src,
                                                long strideHalfs, int tid)
{
#pragma unroll
    for (int i = 0; i < 2; i++) {
        int flat = i * 256 + tid;
        int row = flat >> 3;
        int seg = flat & 7;
        uint32_t off = (uint32_t)(row * 128 + ((seg * 16) ^ ((row & 7) * 16)));
        CP_ASYNC16(dst + off, src + (long)row * strideHalfs + seg * 8);
    }
}

// ============ scores: S[bh][q][k] = (Q . K) * SCALE via mma, causal tiles ============
// grid (qt, bh). smem: Q 8KB + 2x8KB K stages = 24KB.
__global__ void __launch_bounds__(256) scores_mma(const __half* __restrict__ qkvh,
                                                  float* __restrict__ scores)
{
    int qt = blockIdx.x, bh = blockIdx.y;
    int b = bh >> 4, h = bh & 15;
    int q0 = qt * 64;
    extern __shared__ char smem[];
    uint32_t sQ = smem_u32(smem);
    uint32_t sKb = sQ + 8192;
    int tid = threadIdx.x, lane = tid & 31, w = tid >> 5;
    int warpM = (w >> 1) * 16, warpN = (w & 1) * 32;

    const __half* qbase = qkvh + (long)(b * Tn + q0) * E3n + HDn * h;
    const __half* kbase = qkvh + (long)(b * Tn) * E3n + En + HDn * h;

    load_tile64x128(sQ, qbase, E3n, tid);
    load_tile64x128(sKb, kbase, E3n, tid);
    CP_COMMIT();
    if (qt >= 1) load_tile64x128(sKb + 8192, kbase + (long)64 * E3n, E3n, tid);
    CP_COMMIT();

    int mrow = warpM + (lane & 7) + ((lane >> 3) & 1) * 8;
    int acol = (lane >> 4) * 16;
    int nrow0 = warpN + (lane & 7) + ((lane >> 4) & 1) * 8;
    int bcol = ((lane >> 3) & 1) * 16;

    for (int kt = 0; kt <= qt; kt++) {
        CP_WAIT1();
        __syncthreads();
        uint32_t sK = sKb + (kt & 1) * 8192;
        float c[4][4];
#pragma unroll
        for (int i = 0; i < 4; i++)
#pragma unroll
            for (int j = 0; j < 4; j++) c[i][j] = 0.0f;
#pragma unroll
        for (int ks = 0; ks < 4; ks++) {
            uint32_t af[4];
            {
                int m = mrow;
                uint32_t addr = sQ + m * 128 + ((ks * 32 + acol) ^ ((m & 7) * 16));
                LDSM_X4(af[0], af[1], af[2], af[3], addr);
            }
            uint32_t bf[4][2];
#pragma unroll
            for (int nb = 0; nb < 2; nb++) {
                int n = nrow0 + nb * 16;
                uint32_t addr = sK + n * 128 + ((ks * 32 + bcol) ^ ((n & 7) * 16));
                uint32_t r0, r1, r2, r3;
                LDSM_X4(r0, r1, r2, r3, addr);
                bf[nb * 2][0] = r0;     bf[nb * 2][1] = r1;
                bf[nb * 2 + 1][0] = r2; bf[nb * 2 + 1][1] = r3;
            }
#pragma unroll
            for (int ni = 0; ni < 4; ni++)
                MMA16816(c[ni], af, bf[ni]);
        }
        {
            int q = q0 + warpM + (lane >> 2);
            long ro = ((long)bh * Tn + q) * Tn + kt * 64;
#pragma unroll
            for (int ni = 0; ni < 4; ni++) {
                int col = warpN + ni * 8 + (lane & 3) * 2;
                float2 p0; p0.x = c[ni][0] * SCALE_Q; p0.y = c[ni][1] * SCALE_Q;
                float2 p1; p1.x = c[ni][2] * SCALE_Q; p1.y = c[ni][3] * SCALE_Q;
                *(float2*)(scores + ro + col) = p0;
                *(float2*)(scores + ro + 8 * Tn + col) = p1;
            }
        }
        __syncthreads();
        if (kt + 2 <= qt)
            load_tile64x128(sKb + (kt & 1) * 8192, kbase + (long)(kt + 2) * 64 * E3n, E3n, tid);
        CP_COMMIT();
    }
}

// ---------- warp-per-row masked softmax: fp32 scores -> fp16 P ----------
__global__ void __launch_bounds__(256) softmax_warp(const float* __restrict__ scores,
                                                    __half* __restrict__ ph)
{
    int wz = blockIdx.x * 8 + (threadIdx.x >> 5);
    int lane = threadIdx.x & 31;
    int q = wz & (Tn - 1);
    int bh = wz >> 10;
    int b = bh >> 4;
    const float* row = scores + (long)wz * Tn;
    int kmax = min(q, g_len[b] - 1);
    int kwr = q | 63;

    float4 vals[8];
    float mx = -3.4e38f;
#pragma unroll
    for (int c = 0; c < 8; c++) {
        int k4 = c * 128 + lane * 4;
        float4 f;
        if (k4 <= kmax) f = *(const float4*)(row + k4);
        else f.x = f.y = f.z = f.w = -3.4e38f;
        if (k4 + 1 > kmax) f.y = -3.4e38f;
        if (k4 + 2 > kmax) f.z = -3.4e38f;
        if (k4 + 3 > kmax) f.w = -3.4e38f;
        vals[c] = f;
        mx = fmaxf(mx, fmaxf(fmaxf(f.x, f.y), fmaxf(f.z, f.w)));
    }
#pragma unroll
    for (int s = 16; s > 0; s >>= 1)
        mx = fmaxf(mx, __shfl_xor_sync(0xFFFFFFFFu, mx, s));

    float sum = 0.0f;
#pragma unroll
    for (int c = 0; c < 8; c++) {
        float4 f = vals[c];
        f.x = (f.x > -3.0e38f) ? expf(f.x - mx) : 0.0f;
        f.y = (f.y > -3.0e38f) ? expf(f.y - mx) : 0.0f;
        f.z = (f.z > -3.0e38f) ? expf(f.z - mx) : 0.0f;
        f.w = (f.w > -3.0e38f) ? expf(f.w - mx) : 0.0f;
        vals[c] = f;
        sum += f.x + f.y + f.z + f.w;
    }
#pragma unroll
    for (int s = 16; s > 0; s >>= 1)
        sum += __shfl_xor_sync(0xFFFFFFFFu, sum, s);
    float inv = 1.0f / sum;

    __half* prow = ph + (long)wz * Tn;
#pragma unroll
    for (int c = 0; c < 8; c++) {
        int k4 = c * 128 + lane * 4;
        if (k4 > kwr) continue;
        float4 f = vals[c];
        __align__(8) __half o[4];
        o[0] = __float2half_rn(f.x * inv);
        o[1] = __float2half_rn(f.y * inv);
        o[2] = __float2half_rn(f.z * inv);
        o[3] = __float2half_rn(f.w * inv);
        *(uint2*)(prow + k4) = *(const uint2*)o;
    }
}

// ---------- build V^T: vth[bh][d][k] fp16 from qkvh ----------
__global__ void __launch_bounds__(256) vt_kernel(const __half* __restrict__ qkvh,
                                                 __half* __restrict__ vth)
{
    int kt = blockIdx.x, bh = blockIdx.y;
    int b = bh >> 4, h = bh & 15;
    __shared__ __half Vs[64][72];
    int tid = threadIdx.x;
    const __half* vbase = qkvh + (long)(b * Tn + kt * 64) * E3n + 2 * En + HDn * h;
    // read 64 rows x 64 halfs
    for (int i = tid; i < 512; i += 256) {
        int r = i >> 3, seg = i & 7;            // 8 x uint4 per row
        uint4 u = *(const uint4*)(vbase + (long)r * E3n + seg * 8);
        *(uint4*)&Vs[r][seg * 8] = u;
    }
    __syncthreads();
    for (int i = tid; i < 4096; i += 256) {
        int d = i >> 6, k = i & 63;
        vth[((long)(bh * 64 + d)) * Tn + kt * 64 + k] = Vs[k][d];
    }
}

// ============ PV: O[q][d] = sum_k P . V via mma, accumulate across causal tiles ============
// grid (qt, bh). smem: 2 stages x (P 8KB + V 8KB) = 32KB.
__global__ void __launch_bounds__(256) pv_mma(const __half* __restrict__ ph,
                                              const __half* __restrict__ vth,
                                              __half* __restrict__ attnh)
{
    int qt = blockIdx.x, bh = blockIdx.y;
    int b = bh >> 4, h = bh & 15;
    int q0 = qt * 64;
    extern __shared__ char smem[];
    uint32_t s0 = smem_u32(smem);
    int tid = threadIdx.x, lane = tid & 31, w = tid >> 5;
    int warpM = (w >> 1) * 16, warpN = (w & 1) * 32;

    const __half* pbase = ph + (long)(bh * Tn + q0) * Tn;
    const __half* vbase = vth + (long)(bh * 64) * Tn;

    load_tile64x128(s0, pbase, Tn, tid);
    load_tile64x128(s0 + 8192, vbase, Tn, tid);
    CP_COMMIT();
    if (qt >= 1) {
        load_tile64x128(s0 + 16384, pbase + 64, Tn, tid);
        load_tile64x128(s0 + 24576, vbase + 64, Tn, tid);
    }
    CP_COMMIT();

    int mrow = warpM + (lane & 7) + ((lane >> 3) & 1) * 8;
    int acol = (lane >> 4) * 16;
    int nrow0 = warpN + (lane & 7) + ((lane >> 4) & 1) * 8;
    int bcol = ((lane >> 3) & 1) * 16;

    float c[4][4];
#pragma unroll
    for (int i = 0; i < 4; i++)
#pragma unroll
        for (int j = 0; j < 4; j++) c[i][j] = 0.0f;

    for (int kt = 0; kt <= qt; kt++) {
        CP_WAIT1();
        __syncthreads();
        uint32_t sP = s0 + (kt & 1) * 16384;
        uint32_t sV = sP + 8192;
#pragma unroll
        for (int ks = 0; ks < 4; ks++) {
            uint32_t af[4];
            {
                int m = mrow;
                uint32_t addr = sP + m * 128 + ((ks * 32 + acol) ^ ((m & 7) * 16));
                LDSM_X4(af[0], af[1], af[2], af[3], addr);
            }
            uint32_t bf[4][2];
#pragma unroll
            for (int nb = 0; nb < 2; nb++) {
                int n = nrow0 + nb * 16;
                uint32_t addr = sV + n * 128 + ((ks * 32 + bcol) ^ ((n & 7) * 16));
                uint32_t r0, r1, r2, r3;
                LDSM_X4(r0, r1, r2, r3, addr);
                bf[nb * 2][0] = r0;     bf[nb * 2][1] = r1;
                bf[nb * 2 + 1][0] = r2; bf[nb * 2 + 1][1] = r3;
            }
#pragma unroll
            for (int ni = 0; ni < 4; ni++)
                MMA16816(c[ni], af, bf[ni]);
        }
        __syncthreads();
        if (kt + 2 <= qt) {
            uint32_t dst = s0 + (kt & 1) * 16384;
            load_tile64x128(dst, pbase + (long)(kt + 2) * 64, Tn, tid);
            load_tile64x128(dst + 8192, vbase + (long)(kt + 2) * 64, Tn, tid);
        }
        CP_COMMIT();
    }

    // epilogue: fp16 attn
    int q = q0 + warpM + (lane >> 2);
    long tok = (long)b * Tn + q;
#pragma unroll
    for (int ni = 0; ni < 4; ni++) {
        int gcol = h * 64 + warpN + ni * 8 + (lane & 3) * 2;
        __align__(4) __half o[2];
        o[0] = __float2half_rn(c[ni][0]); o[1] = __float2half_rn(c[ni][1]);
        *(uint32_t*)(attnh + tok * En + gcol) = *(const uint32_t*)o;
        o[0] = __float2half_rn(c[ni][2]); o[1] = __float2half_rn(c[ni][3]);
        *(uint32_t*)(attnh + (tok + 8) * En + gcol) = *(const uint32_t*)o;
    }
}

// ---------------- residual add + LayerNorm (optional fp16 out) ----------------
__global__ void __launch_bounds__(256) ln_kernel(const float* __restrict__ res,
                                                 const float* __restrict__ y,
                                                 const float* __restrict__ w,
                                                 const float* __restrict__ bb,
                                                 float* __restrict__ out,
                                                 __half* __restrict__ outs)
{
    long r = blockIdx.x;
    int t = threadIdx.x;
    const float* r0 = res + r * En;
    const float* y0 = y + r * En;
    __shared__ float rs[256], rss[256];
    float v[4];
    float s = 0.0f, ss = 0.0f;
#pragma unroll
    for (int i = 0; i < 4; i++) {
        int idx = t + i * 256;
        v[i] = r0[idx] + y0[idx];
        s += v[i];
        ss += v[i] * v[i];
    }
    rs[t] = s; rss[t] = ss; __syncthreads();
    for (int sh = 128; sh > 0; sh >>= 1) {
        if (t < sh) { rs[t] += rs[t + sh]; rss[t] += rss[t + sh]; }
        __syncthreads();
    }
    float mean = rs[0] * (1.0f / En);
    float var  = rss[0] * (1.0f / En) - mean * mean;
    float inv  = rsqrtf(var + LN_EPS);
#pragma unroll
    for (int i = 0; i < 4; i++) {
        int idx = t + i * 256;
        float o = w[idx] * (v[i] - mean) * inv + bb[idx];
        out[r * En + idx] = o;
        if (outs) outs[r * En + idx] = __float2half_rn(o);
    }
}

// ---------------- launch ----------------
static inline void cvt(const float* src, __half* dst, long n) {
    long n4 = n >> 2;
    cvt_kernel<<<(unsigned)((n4 + 255) / 256), 256>>>(src, dst, n4);
}

extern "C" void kernel_launch(void* const* d_in, const int* in_sizes, int n_in,
                              void* d_out, int out_size)
{
    const float* x     = (const float*)d_in[0];
    const float* in_w  = (const float*)d_in[1];
    const float* in_b  = (const float*)d_in[2];
    const float* out_w = (const float*)d_in[3];
    const float* out_b = (const float*)d_in[4];
    const float* fc1_w = (const float*)d_in[5];
    const float* fc1_b = (const float*)d_in[6];
    const float* fc2_w = (const float*)d_in[7];
    const float* fc2_b = (const float*)d_in[8];
    const float* ln1_w = (const float*)d_in[9];
    const float* ln1_b = (const float*)d_in[10];
    const float* ln2_w = (const float*)d_in[11];
    const float* ln2_b = (const float*)d_in[12];
    const void*  pad_mask = d_in[13];
    float* out = (float*)d_out;

    float *scores, *tmp, *x1;
    cudaGetSymbolAddress((void**)&scores, g_scores);
    cudaGetSymbolAddress((void**)&tmp,    g_tmp);
    cudaGetSymbolAddress((void**)&x1,     g_x1);
    __half *qkvh, *ph, *vth, *xh, *attnh, *x1h, *ffnh, *inwh, *outwh, *fc1wh, *fc2wh;
    cudaGetSymbolAddress((void**)&qkvh,  g_qkvh);
    cudaGetSymbolAddress((void**)&ph,    g_ph);
    cudaGetSymbolAddress((void**)&vth,   g_vth);
    cudaGetSymbolAddress((void**)&xh,    g_xh);
    cudaGetSymbolAddress((void**)&attnh, g_attnh);
    cudaGetSymbolAddress((void**)&x1h,   g_x1h);
    cudaGetSymbolAddress((void**)&ffnh,  g_ffnh);
    cudaGetSymbolAddress((void**)&inwh,  g_inwh);
    cudaGetSymbolAddress((void**)&outwh, g_outwh);
    cudaGetSymbolAddress((void**)&fc1wh, g_fc1wh);
    cudaGetSymbolAddress((void**)&fc2wh, g_fc2wh);

    const int GSMEM = GST * STAGE_BYTES;   // 96 KB
    cudaFuncSetAttribute(gemm_mma<false, false>, cudaFuncAttributeMaxDynamicSharedMemorySize, GSMEM);
    cudaFuncSetAttribute(gemm_mma<false, true>,  cudaFuncAttributeMaxDynamicSharedMemorySize, GSMEM);
    cudaFuncSetAttribute(gemm_mma<true, true>,   cudaFuncAttributeMaxDynamicSharedMemorySize, GSMEM);
    cudaFuncSetAttribute(scores_mma, cudaFuncAttributeMaxDynamicSharedMemorySize, 24576);
    cudaFuncSetAttribute(pv_mma,     cudaFuncAttributeMaxDynamicSharedMemorySize, 32768);

    // 0. sequence lengths
    len_kernel<<<1, 256>>>(pad_mask);

    // 1. QKV projection -> fp16 qkvh
    cvt(x, xh, (long)TOK * En);
    cvt(in_w, inwh, (long)E3n * En);
    gemm_mma<false, true><<<dim3(E3n / 128, TOK / 128), 256, GSMEM>>>(xh, inwh, in_b, qkvh, E3n, En);

    // 2. attention: tensor-core scores, warp softmax, tensor-core PV
    vt_kernel<<<dim3(Tn / 64, BHn), 256>>>(qkvh, vth);
    scores_mma<<<dim3(Tn / 64, BHn), 256, 24576>>>(qkvh, scores);
    softmax_warp<<<BHn * Tn / 8, 256>>>(scores, ph);
    pv_mma<<<dim3(Tn / 64, BHn), 256, 32768>>>(ph, vth, attnh);

    // 3. output projection
    cvt(out_w, outwh, (long)En * En);
    gemm_mma<false, false><<<dim3(En / 128, TOK / 128), 256, GSMEM>>>(attnh, outwh, out_b, tmp, En, En);

    // 4. residual + LN1
    ln_kernel<<<TOK, 256>>>(x, tmp, ln1_w, ln1_b, x1, x1h);

    // 5. FC1 + ReLU -> fp16 ffnh
    cvt(fc1_w, fc1wh, (long)FFn * En);
    gemm_mma<true, true><<<dim3(FFn / 128, TOK / 128), 256, GSMEM>>>(x1h, fc1wh, fc1_b, ffnh, FFn, En);

    // 6. FC2
    cvt(fc2_w, fc2wh, (long)En * FFn);
    gemm_mma<false, false><<<dim3(En / 128, TOK / 128), 256, GSMEM>>>(ffnh, fc2wh, fc2_b, tmp, En, FFn);

    // 7. residual + LN2 -> out
    ln_kernel<<<TOK, 256>>>(x1, tmp, ln2_w, ln2_b, out, (half*)nullptr);
}

// round 8
// speedup vs baseline: 8.4952x; 1.1696x over previous
#include <cuda_runtime.h>
#include <cuda_fp16.h>
#include <stdint.h>
#include <math.h>

// Problem constants
#define Bn 8
#define Tn 1024
#define En 1024
#define Hn 16
#define HDn 64
#define FFn 4096
#define E3n 3072
#define TOK 8192          // B*T
#define BHn 128           // B*H
#define SCALE_Q 0.125f    // 64^-0.5
#define LN_EPS 1e-12f

// ======================= PTX helpers (sm_80+ features only) =======================
__device__ __forceinline__ uint32_t smem_u32(const void* p) {
    uint32_t a;
    asm("{ .reg .u64 t; cvta.to.shared.u64 t, %1; cvt.u32.u64 %0, t; }" : "=r"(a) : "l"(p));
    return a;
}
#define CP_ASYNC16(dst, src) \
    asm volatile("cp.async.cg.shared.global [%0], [%1], 16;" :: "r"(dst), "l"(src) : "memory")
#define CP_COMMIT() asm volatile("cp.async.commit_group;" ::: "memory")
#define CP_WAIT2()  asm volatile("cp.async.wait_group 2;" ::: "memory")
#define CP_WAIT1()  asm volatile("cp.async.wait_group 1;" ::: "memory")
#define LDSM_X4(r0, r1, r2, r3, addr) \
    asm volatile("ldmatrix.sync.aligned.m8n8.x4.shared.b16 {%0,%1,%2,%3}, [%4];" \
        : "=r"(r0), "=r"(r1), "=r"(r2), "=r"(r3) : "r"(addr))
#define LDSM_X4_T(r0, r1, r2, r3, addr) \
    asm volatile("ldmatrix.sync.aligned.m8n8.x4.trans.shared.b16 {%0,%1,%2,%3}, [%4];" \
        : "=r"(r0), "=r"(r1), "=r"(r2), "=r"(r3) : "r"(addr))
#define MMA16816(d, a, b) \
    asm volatile("mma.sync.aligned.m16n8k16.row.col.f32.f16.f16.f32 " \
        "{%0,%1,%2,%3}, {%4,%5,%6,%7}, {%8,%9}, {%0,%1,%2,%3};" \
        : "+f"((d)[0]), "+f"((d)[1]), "+f"((d)[2]), "+f"((d)[3]) \
        : "r"((a)[0]), "r"((a)[1]), "r"((a)[2]), "r"((a)[3]), "r"((b)[0]), "r"((b)[1]))

// ---------------- static scratch (no allocations allowed) ----------------
__device__ __half g_qkvh[(long)TOK * E3n];             // fp16 qkv
__device__ float g_tmp[TOK * En];
__device__ float g_x1[TOK * En];
__device__ int   g_len[Bn];
__device__ __half g_xh[(long)TOK * En];
__device__ __half g_attnh[(long)TOK * En];
__device__ __half g_x1h[(long)TOK * En];
__device__ __half g_ffnh[(long)TOK * FFn];
__device__ __half g_inwh[(long)E3n * En];
__device__ __half g_outwh[(long)En * En];
__device__ __half g_fc1wh[(long)FFn * En];
__device__ __half g_fc2wh[(long)En * FFn];

// ---------------- fp32 -> fp16 convert ----------------
__global__ void __launch_bounds__(256) cvt_kernel(const float* __restrict__ src,
                                                  __half* __restrict__ dst, long n4)
{
    long i = (long)blockIdx.x * 256 + threadIdx.x;
    if (i >= n4) return;
    float4 v = ((const float4*)src)[i];
    __align__(8) __half o[4];
    o[0] = __float2half_rn(v.x); o[1] = __float2half_rn(v.y);
    o[2] = __float2half_rn(v.z); o[3] = __float2half_rn(v.w);
    ((uint2*)dst)[i] = *(const uint2*)o;
}

// ---------------- mask dtype detection + lengths ----------------
__global__ void len_kernel(const void* maskp) {
    __shared__ int s_kind;   // 0=i32, 1=u8, 2=f32
    __shared__ int s_len[Bn];
    int t = threadIdx.x;
    if (t == 0) s_kind = 0;
    if (t < Bn) s_len[t] = Tn;
    __syncthreads();
    const unsigned int* w = (const unsigned int*)maskp;
    for (int i = t; i < 2048; i += blockDim.x) {
        unsigned int v = w[i];
        if (v == 0x3F800000u) atomicMax(&s_kind, 2);
        else if (v > 1u)      atomicMax(&s_kind, 1);
    }
    __syncthreads();
    int kind = s_kind;
    const unsigned char* mb = (const unsigned char*)maskp;
    const int* mi = (const int*)maskp;
    const float* mf = (const float*)maskp;
    for (int i = t; i < Bn * Tn; i += blockDim.x) {
        int b = i >> 10, tt = i & (Tn - 1);
        int m;
        if (kind == 1)      m = (int)mb[i];
        else if (kind == 2) m = (mf[i] != 0.0f);
        else                m = mi[i];
        if (m) atomicMin(&s_len[b], tt);
    }
    __syncthreads();
    if (t < Bn) g_len[t] = s_len[t];
}

// ============ mma.sync GEMM (proven): C[M,N] = A[M,K](fp16) * B[N,K](fp16)^T + bias ============
#define GST 3
#define STAGE_BYTES 32768

template<bool RELU, bool HALF_OUT>
__global__ void __launch_bounds__(256) gemm_mma(
    const __half* __restrict__ A2,
    const __half* __restrict__ B2,
    const float* __restrict__ bias,
    void* __restrict__ Cv, int N, int K2)
{
    extern __shared__ char smem[];
    uint32_t sb = smem_u32(smem);
    int tid = threadIdx.x, lane = tid & 31, w = tid >> 5;
    int m0 = blockIdx.y * 128, n0 = blockIdx.x * 128;
    int warpM = (w >> 2) * 64, warpN = (w & 3) * 32;
    const int CH = K2 >> 6;

    auto issue = [&](int c) {
        if (c < CH) {
            uint32_t base = sb + (c % GST) * STAGE_BYTES;
            long kb = (long)c * 64;
#pragma unroll
            for (int i = 0; i < 4; i++) {
                int flat = i * 256 + tid;
                int row = flat >> 3;
                int seg = flat & 7;
                uint32_t off = (uint32_t)(row * 128 + ((seg * 16) ^ ((row & 7) * 16)));
                CP_ASYNC16(base + off,         A2 + (long)(m0 + row) * K2 + kb + seg * 8);
                CP_ASYNC16(base + 16384 + off, B2 + (long)(n0 + row) * K2 + kb + seg * 8);
            }
        }
        CP_COMMIT();
    };
    issue(0); issue(1); issue(2);

    float acc[4][4][4];
#pragma unroll
    for (int i = 0; i < 4; i++)
#pragma unroll
        for (int j = 0; j < 4; j++)
#pragma unroll
            for (int k = 0; k < 4; k++) acc[i][j][k] = 0.0f;

    int mrow = warpM + (lane & 7) + ((lane >> 3) & 1) * 8;
    int acol = (lane >> 4) * 16;
    int nrow = warpN + (lane & 7) + ((lane >> 4) & 1) * 8;
    int bcol = ((lane >> 3) & 1) * 16;

    for (int c = 0; c < CH; c++) {
        CP_WAIT2();
        __syncthreads();
        uint32_t sA = sb + (c % GST) * STAGE_BYTES;
        uint32_t sB = sA + 16384;
#pragma unroll
        for (int ks = 0; ks < 4; ks++) {
            uint32_t af[4][4];
#pragma unroll
            for (int mi = 0; mi < 4; mi++) {
                int m = mrow + mi * 16;
                uint32_t addr = sA + m * 128 + ((ks * 32 + acol) ^ ((m & 7) * 16));
                LDSM_X4(af[mi][0], af[mi][1], af[mi][2], af[mi][3], addr);
            }
            uint32_t bf[4][2];
#pragma unroll
            for (int nb = 0; nb < 2; nb++) {
                int n = nrow + nb * 16;
                uint32_t addr = sB + n * 128 + ((ks * 32 + bcol) ^ ((n & 7) * 16));
                uint32_t r0, r1, r2, r3;
                LDSM_X4(r0, r1, r2, r3, addr);
                bf[nb * 2][0] = r0;     bf[nb * 2][1] = r1;
                bf[nb * 2 + 1][0] = r2; bf[nb * 2 + 1][1] = r3;
            }
#pragma unroll
            for (int mi = 0; mi < 4; mi++)
#pragma unroll
                for (int ni = 0; ni < 4; ni++)
                    MMA16816(acc[mi][ni], af[mi], bf[ni]);
        }
        __syncthreads();
        issue(c + 3);
    }

#pragma unroll
    for (int mi = 0; mi < 4; mi++) {
        int r = m0 + warpM + mi * 16 + (lane >> 2);
#pragma unroll
        for (int ni = 0; ni < 4; ni++) {
            int col = n0 + warpN + ni * 8 + (lane & 3) * 2;
            float b0 = bias[col], b1 = bias[col + 1];
            float v0 = acc[mi][ni][0] + b0, v1 = acc[mi][ni][1] + b1;
            float v2 = acc[mi][ni][2] + b0, v3 = acc[mi][ni][3] + b1;
            if (RELU) {
                v0 = fmaxf(v0, 0.0f); v1 = fmaxf(v1, 0.0f);
                v2 = fmaxf(v2, 0.0f); v3 = fmaxf(v3, 0.0f);
            }
            if (HALF_OUT) {
                __half* C = (__half*)Cv;
                __align__(4) __half o[2];
                o[0] = __float2half_rn(v0); o[1] = __float2half_rn(v1);
                *(uint32_t*)(C + (long)r * N + col) = *(const uint32_t*)o;
                o[0] = __float2half_rn(v2); o[1] = __float2half_rn(v3);
                *(uint32_t*)(C + (long)(r + 8) * N + col) = *(const uint32_t*)o;
            } else {
                float* C = (float*)Cv;
                float2 p0; p0.x = v0; p0.y = v1;
                float2 p1; p1.x = v2; p1.y = v3;
                *(float2*)(C + (long)r * N + col) = p0;
                *(float2*)(C + (long)(r + 8) * N + col) = p1;
            }
        }
    }
}

// ---------------- shared tile loader: 64 rows x 128B, swizzled ----------------
__device__ __forceinline__ void load_tile64x128(uint32_t dst, const __half* src,
                                                long strideHalfs, int tid)
{
#pragma unroll
    for (int i = 0; i < 2; i++) {
        int flat = i * 256 + tid;
        int row = flat >> 3;
        int seg = flat & 7;
        uint32_t off = (uint32_t)(row * 128 + ((seg * 16) ^ ((row & 7) * 16)));
        CP_ASYNC16(dst + off, src + (long)row * strideHalfs + seg * 8);
    }
}

// ============ fused flash attention: qkvh -> attnh (fp16) ============
// grid (T/128 q-blocks, B*H). 8 warps x m16 = 128 q rows. K-tiles of 64, causal.
// smem: Q 16KB + K 2x8KB + V 2x8KB = 48KB.
__global__ void __launch_bounds__(256) fa_kernel(const __half* __restrict__ qkvh,
                                                 __half* __restrict__ attnh)
{
    int qb = blockIdx.x, bh = blockIdx.y;
    int b = bh >> 4, h = bh & 15;
    int q0 = qb * 128;
    extern __shared__ char smem[];
    uint32_t sQ = smem_u32(smem);
    uint32_t sK = sQ + 16384;
    uint32_t sV = sK + 16384;
    int tid = threadIdx.x, lane = tid & 31, w = tid >> 5;

    const __half* qbase = qkvh + (long)(b * Tn + q0) * E3n + HDn * h;
    const __half* kbase = qkvh + (long)(b * Tn) * E3n + En + HDn * h;
    const __half* vbase = qkvh + (long)(b * Tn) * E3n + 2 * En + HDn * h;
    int len = g_len[b];
    const int KT = (q0 + 127) >> 6;     // inclusive last k-tile (>=1)

    load_tile64x128(sQ, qbase, E3n, tid);
    load_tile64x128(sQ + 8192, qbase + (long)64 * E3n, E3n, tid);
    load_tile64x128(sK, kbase, E3n, tid);
    load_tile64x128(sV, vbase, E3n, tid);
    CP_COMMIT();
    load_tile64x128(sK + 8192, kbase + (long)64 * E3n, E3n, tid);
    load_tile64x128(sV + 8192, vbase + (long)64 * E3n, E3n, tid);
    CP_COMMIT();

    int qrow = w * 16 + (lane >> 2);                     // row in [0,128)
    int kmax0 = min(q0 + qrow, len - 1);
    int kmax1 = min(q0 + qrow + 8, len - 1);
    int mrow = w * 16 + (lane & 7) + ((lane >> 3) & 1) * 8;  // Q A-ldsm row
    int acol = (lane >> 4) * 16;
    int nrow0 = (lane & 7) + ((lane >> 4) & 1) * 8;          // K B-ldsm row
    int bcol = ((lane >> 3) & 1) * 16;
    int wmaskref = min(q0 + w * 16, len - 1);            // min kmax over warp rows

    float m0r = -1e30f, m1r = -1e30f, l0 = 0.0f, l1 = 0.0f;
    float o[8][4];
#pragma unroll
    for (int i = 0; i < 8; i++)
#pragma unroll
        for (int j = 0; j < 4; j++) o[i][j] = 0.0f;

    for (int kt = 0; kt <= KT; kt++) {
        CP_WAIT1();
        __syncthreads();
        uint32_t sk = sK + (kt & 1) * 8192;
        uint32_t sv = sV + (kt & 1) * 8192;

        // ---- S = Q . K^T : m16 x n64 per warp ----
        float c[8][4];
#pragma unroll
        for (int i = 0; i < 8; i++)
#pragma unroll
            for (int j = 0; j < 4; j++) c[i][j] = 0.0f;
#pragma unroll
        for (int ks = 0; ks < 4; ks++) {
            uint32_t af[4];
            LDSM_X4(af[0], af[1], af[2], af[3],
                    sQ + mrow * 128 + ((ks * 32 + acol) ^ ((mrow & 7) * 16)));
#pragma unroll
            for (int nb = 0; nb < 4; nb++) {
                int n = nrow0 + nb * 16;
                uint32_t r0, r1, r2, r3;
                LDSM_X4(r0, r1, r2, r3, sk + n * 128 + ((ks * 32 + bcol) ^ ((n & 7) * 16)));
                uint32_t bfa[2] = { r0, r1 }, bfb[2] = { r2, r3 };
                MMA16816(c[nb * 2], af, bfa);
                MMA16816(c[nb * 2 + 1], af, bfb);
            }
        }

        // ---- scale + mask + tile row max ----
        bool needmask = (kt * 64 + 63 > wmaskref);
        int colb = kt * 64 + (lane & 3) * 2;
        float mt0 = -1e30f, mt1 = -1e30f;
#pragma unroll
        for (int nf = 0; nf < 8; nf++) {
            c[nf][0] *= SCALE_Q; c[nf][1] *= SCALE_Q;
            c[nf][2] *= SCALE_Q; c[nf][3] *= SCALE_Q;
            if (needmask) {
                int col = colb + nf * 8;
                if (col > kmax0)     c[nf][0] = -1e30f;
                if (col + 1 > kmax0) c[nf][1] = -1e30f;
                if (col > kmax1)     c[nf][2] = -1e30f;
                if (col + 1 > kmax1) c[nf][3] = -1e30f;
            }
            mt0 = fmaxf(mt0, fmaxf(c[nf][0], c[nf][1]));
            mt1 = fmaxf(mt1, fmaxf(c[nf][2], c[nf][3]));
        }
        mt0 = fmaxf(mt0, __shfl_xor_sync(0xFFFFFFFFu, mt0, 1));
        mt0 = fmaxf(mt0, __shfl_xor_sync(0xFFFFFFFFu, mt0, 2));
        mt1 = fmaxf(mt1, __shfl_xor_sync(0xFFFFFFFFu, mt1, 1));
        mt1 = fmaxf(mt1, __shfl_xor_sync(0xFFFFFFFFu, mt1, 2));

        // ---- online softmax update ----
        float mn0 = fmaxf(m0r, mt0), mn1 = fmaxf(m1r, mt1);
        float cor0 = __expf(m0r - mn0), cor1 = __expf(m1r - mn1);
        m0r = mn0; m1r = mn1;
        float s0 = 0.0f, s1 = 0.0f;
        uint32_t ph0[8], ph1[8];
#pragma unroll
        for (int nf = 0; nf < 8; nf++) {
            float e0 = __expf(c[nf][0] - mn0);
            float e1 = __expf(c[nf][1] - mn0);
            float e2 = __expf(c[nf][2] - mn1);
            float e3 = __expf(c[nf][3] - mn1);
            s0 += e0 + e1; s1 += e2 + e3;
            __half2 hp0 = __floats2half2_rn(e0, e1);
            __half2 hp1 = __floats2half2_rn(e2, e3);
            ph0[nf] = *(uint32_t*)&hp0;
            ph1[nf] = *(uint32_t*)&hp1;
        }
        s0 += __shfl_xor_sync(0xFFFFFFFFu, s0, 1);
        s0 += __shfl_xor_sync(0xFFFFFFFFu, s0, 2);
        s1 += __shfl_xor_sync(0xFFFFFFFFu, s1, 1);
        s1 += __shfl_xor_sync(0xFFFFFFFFu, s1, 2);
        l0 = l0 * cor0 + s0;
        l1 = l1 * cor1 + s1;
#pragma unroll
        for (int nf = 0; nf < 8; nf++) {
            o[nf][0] *= cor0; o[nf][1] *= cor0;
            o[nf][2] *= cor1; o[nf][3] *= cor1;
        }

        // ---- O += P . V  (V via ldmatrix.trans from [k][d] tile) ----
#pragma unroll
        for (int kf = 0; kf < 4; kf++) {
            uint32_t a[4] = { ph0[kf * 2], ph1[kf * 2], ph0[kf * 2 + 1], ph1[kf * 2 + 1] };
            int krow = kf * 16 + ((lane >> 3) & 1) * 8 + (lane & 7);
#pragma unroll
            for (int db = 0; db < 2; db++) {
                int dcolb = ((lane >> 4) * 8 + db * 32) * 2;
                uint32_t r0, r1, r2, r3;
                LDSM_X4_T(r0, r1, r2, r3,
                          sv + krow * 128 + (dcolb ^ ((krow & 7) * 16)));
                uint32_t bfa[2] = { r0, r1 }, bfb[2] = { r2, r3 };
                MMA16816(o[db * 4 + 0], a, bfa);
                MMA16816(o[db * 4 + 1], a, bfb);
                int dcolb2 = dcolb + 32;
                LDSM_X4_T(r0, r1, r2, r3,
                          sv + krow * 128 + (dcolb2 ^ ((krow & 7) * 16)));
                uint32_t bfc[2] = { r0, r1 }, bfd[2] = { r2, r3 };
                MMA16816(o[db * 4 + 2], a, bfc);
                MMA16816(o[db * 4 + 3], a, bfd);
            }
        }

        __syncthreads();
        if (kt + 2 <= KT) {
            uint32_t dk = sK + (kt & 1) * 8192;
            uint32_t dv = sV + (kt & 1) * 8192;
            load_tile64x128(dk, kbase + (long)(kt + 2) * 64 * E3n, E3n, tid);
            load_tile64x128(dv, vbase + (long)(kt + 2) * 64 * E3n, E3n, tid);
        }
        CP_COMMIT();
    }

    // ---- epilogue: O / l -> fp16 attn ----
    float inv0 = 1.0f / l0, inv1 = 1.0f / l1;
    long tok = (long)b * Tn + q0 + qrow;
#pragma unroll
    for (int nf = 0; nf < 8; nf++) {
        int d = h * 64 + nf * 8 + (lane & 3) * 2;
        __half2 w0 = __floats2half2_rn(o[nf][0] * inv0, o[nf][1] * inv0);
        __half2 w1 = __floats2half2_rn(o[nf][2] * inv1, o[nf][3] * inv1);
        *(uint32_t*)(attnh + tok * En + d) = *(uint32_t*)&w0;
        *(uint32_t*)(attnh + (tok + 8) * En + d) = *(uint32_t*)&w1;
    }
}

// ---------------- residual add + LayerNorm (optional fp16 out) ----------------
__global__ void __launch_bounds__(256) ln_kernel(const float* __restrict__ res,
                                                 const float* __restrict__ y,
                                                 const float* __restrict__ w,
                                                 const float* __restrict__ bb,
                                                 float* __restrict__ out,
                                                 __half* __restrict__ outs)
{
    long r = blockIdx.x;
    int t = threadIdx.x;
    const float* r0 = res + r * En;
    const float* y0 = y + r * En;
    __shared__ float rs[256], rss[256];
    float v[4];
    float s = 0.0f, ss = 0.0f;
#pragma unroll
    for (int i = 0; i < 4; i++) {
        int idx = t + i * 256;
        v[i] = r0[idx] + y0[idx];
        s += v[i];
        ss += v[i] * v[i];
    }
    rs[t] = s; rss[t] = ss; __syncthreads();
    for (int sh = 128; sh > 0; sh >>= 1) {
        if (t < sh) { rs[t] += rs[t + sh]; rss[t] += rss[t + sh]; }
        __syncthreads();
    }
    float mean = rs[0] * (1.0f / En);
    float var  = rss[0] * (1.0f / En) - mean * mean;
    float inv  = rsqrtf(var + LN_EPS);
#pragma unroll
    for (int i = 0; i < 4; i++) {
        int idx = t + i * 256;
        float o = w[idx] * (v[i] - mean) * inv + bb[idx];
        out[r * En + idx] = o;
        if (outs) outs[r * En + idx] = __float2half_rn(o);
    }
}

// ---------------- launch ----------------
static inline void cvt(const float* src, __half* dst, long n) {
    long n4 = n >> 2;
    cvt_kernel<<<(unsigned)((n4 + 255) / 256), 256>>>(src, dst, n4);
}

extern "C" void kernel_launch(void* const* d_in, const int* in_sizes, int n_in,
                              void* d_out, int out_size)
{
    const float* x     = (const float*)d_in[0];
    const float* in_w  = (const float*)d_in[1];
    const float* in_b  = (const float*)d_in[2];
    const float* out_w = (const float*)d_in[3];
    const float* out_b = (const float*)d_in[4];
    const float* fc1_w = (const float*)d_in[5];
    const float* fc1_b = (const float*)d_in[6];
    const float* fc2_w = (const float*)d_in[7];
    const float* fc2_b = (const float*)d_in[8];
    const float* ln1_w = (const float*)d_in[9];
    const float* ln1_b = (const float*)d_in[10];
    const float* ln2_w = (const float*)d_in[11];
    const float* ln2_b = (const float*)d_in[12];
    const void*  pad_mask = d_in[13];
    float* out = (float*)d_out;

    float *tmp, *x1;
    cudaGetSymbolAddress((void**)&tmp, g_tmp);
    cudaGetSymbolAddress((void**)&x1,  g_x1);
    __half *qkvh, *xh, *attnh, *x1h, *ffnh, *inwh, *outwh, *fc1wh, *fc2wh;
    cudaGetSymbolAddress((void**)&qkvh,  g_qkvh);
    cudaGetSymbolAddress((void**)&xh,    g_xh);
    cudaGetSymbolAddress((void**)&attnh, g_attnh);
    cudaGetSymbolAddress((void**)&x1h,   g_x1h);
    cudaGetSymbolAddress((void**)&ffnh,  g_ffnh);
    cudaGetSymbolAddress((void**)&inwh,  g_inwh);
    cudaGetSymbolAddress((void**)&outwh, g_outwh);
    cudaGetSymbolAddress((void**)&fc1wh, g_fc1wh);
    cudaGetSymbolAddress((void**)&fc2wh, g_fc2wh);

    const int GSMEM = GST * STAGE_BYTES;   // 96 KB
    cudaFuncSetAttribute(gemm_mma<false, false>, cudaFuncAttributeMaxDynamicSharedMemorySize, GSMEM);
    cudaFuncSetAttribute(gemm_mma<false, true>,  cudaFuncAttributeMaxDynamicSharedMemorySize, GSMEM);
    cudaFuncSetAttribute(gemm_mma<true, true>,   cudaFuncAttributeMaxDynamicSharedMemorySize, GSMEM);
    cudaFuncSetAttribute(fa_kernel, cudaFuncAttributeMaxDynamicSharedMemorySize, 49152);

    // 0. sequence lengths
    len_kernel<<<1, 256>>>(pad_mask);

    // 1. QKV projection -> fp16 qkvh
    cvt(x, xh, (long)TOK * En);
    cvt(in_w, inwh, (long)E3n * En);
    gemm_mma<false, true><<<dim3(E3n / 128, TOK / 128), 256, GSMEM>>>(xh, inwh, in_b, qkvh, E3n, En);

    // 2. fused flash attention -> fp16 attnh
    fa_kernel<<<dim3(Tn / 128, BHn), 256, 49152>>>(qkvh, attnh);

    // 3. output projection
    cvt(out_w, outwh, (long)En * En);
    gemm_mma<false, false><<<dim3(En / 128, TOK / 128), 256, GSMEM>>>(attnh, outwh, out_b, tmp, En, En);

    // 4. residual + LN1
    ln_kernel<<<TOK, 256>>>(x, tmp, ln1_w, ln1_b, x1, x1h);

    // 5. FC1 + ReLU -> fp16 ffnh
    cvt(fc1_w, fc1wh, (long)FFn * En);
    gemm_mma<true, true><<<dim3(FFn / 128, TOK / 128), 256, GSMEM>>>(x1h, fc1wh, fc1_b, ffnh, FFn, En);

    // 6. FC2
    cvt(fc2_w, fc2wh, (long)En * FFn);
    gemm_mma<false, false><<<dim3(En / 128, TOK / 128), 256, GSMEM>>>(ffnh, fc2wh, fc2_b, tmp, En, FFn);

    // 7. residual + LN2 -> out
    ln_kernel<<<TOK, 256>>>(x1, tmp, ln2_w, ln2_b, out, (half*)nullptr);
}

// round 9
// speedup vs baseline: 8.7609x; 1.0313x over previous
#include <cuda_runtime.h>
#include <cuda_fp16.h>
#include <stdint.h>
#include <math.h>

// Problem constants
#define Bn 8
#define Tn 1024
#define En 1024
#define Hn 16
#define HDn 64
#define FFn 4096
#define E3n 3072
#define TOK 8192          // B*T
#define BHn 128           // B*H
#define SCALE_Q 0.125f    // 64^-0.5
#define LN_EPS 1e-12f

// ======================= PTX helpers (sm_80+ features only) =======================
__device__ __forceinline__ uint32_t smem_u32(const void* p) {
    uint32_t a;
    asm("{ .reg .u64 t; cvta.to.shared.u64 t, %1; cvt.u32.u64 %0, t; }" : "=r"(a) : "l"(p));
    return a;
}
#define CP_ASYNC16(dst, src) \
    asm volatile("cp.async.cg.shared.global [%0], [%1], 16;" :: "r"(dst), "l"(src) : "memory")
#define CP_COMMIT() asm volatile("cp.async.commit_group;" ::: "memory")
#define CP_WAIT1()  asm volatile("cp.async.wait_group 1;" ::: "memory")
#define LDSM_X4(r0, r1, r2, r3, addr) \
    asm volatile("ldmatrix.sync.aligned.m8n8.x4.shared.b16 {%0,%1,%2,%3}, [%4];" \
        : "=r"(r0), "=r"(r1), "=r"(r2), "=r"(r3) : "r"(addr))
#define LDSM_X4_T(r0, r1, r2, r3, addr) \
    asm volatile("ldmatrix.sync.aligned.m8n8.x4.trans.shared.b16 {%0,%1,%2,%3}, [%4];" \
        : "=r"(r0), "=r"(r1), "=r"(r2), "=r"(r3) : "r"(addr))
#define MMA16816(d, a, b) \
    asm volatile("mma.sync.aligned.m16n8k16.row.col.f32.f16.f16.f32 " \
        "{%0,%1,%2,%3}, {%4,%5,%6,%7}, {%8,%9}, {%0,%1,%2,%3};" \
        : "+f"((d)[0]), "+f"((d)[1]), "+f"((d)[2]), "+f"((d)[3]) \
        : "r"((a)[0]), "r"((a)[1]), "r"((a)[2]), "r"((a)[3]), "r"((b)[0]), "r"((b)[1]))

// ---------------- static scratch (no allocations allowed) ----------------
__device__ __half g_qkvh[(long)TOK * E3n];             // fp16 qkv
__device__ float g_tmp[TOK * En];
__device__ float g_x1[TOK * En];
__device__ int   g_len[Bn];
__device__ __half g_xh[(long)TOK * En];
__device__ __half g_attnh[(long)TOK * En];
__device__ __half g_x1h[(long)TOK * En];
__device__ __half g_ffnh[(long)TOK * FFn];
__device__ __half g_inwh[(long)E3n * En];
__device__ __half g_outwh[(long)En * En];
__device__ __half g_fc1wh[(long)FFn * En];
__device__ __half g_fc2wh[(long)En * FFn];

// ---------------- fp32 -> fp16 convert ----------------
__global__ void __launch_bounds__(256) cvt_kernel(const float* __restrict__ src,
                                                  __half* __restrict__ dst, long n4)
{
    long i = (long)blockIdx.x * 256 + threadIdx.x;
    if (i >= n4) return;
    float4 v = ((const float4*)src)[i];
    __align__(8) __half o[4];
    o[0] = __float2half_rn(v.x); o[1] = __float2half_rn(v.y);
    o[2] = __float2half_rn(v.z); o[3] = __float2half_rn(v.w);
    ((uint2*)dst)[i] = *(const uint2*)o;
}

// ---------------- mask dtype detection + lengths ----------------
__global__ void len_kernel(const void* maskp) {
    __shared__ int s_kind;   // 0=i32, 1=u8, 2=f32
    __shared__ int s_len[Bn];
    int t = threadIdx.x;
    if (t == 0) s_kind = 0;
    if (t < Bn) s_len[t] = Tn;
    __syncthreads();
    const unsigned int* w = (const unsigned int*)maskp;
    for (int i = t; i < 2048; i += blockDim.x) {
        unsigned int v = w[i];
        if (v == 0x3F800000u) atomicMax(&s_kind, 2);
        else if (v > 1u)      atomicMax(&s_kind, 1);
    }
    __syncthreads();
    int kind = s_kind;
    const unsigned char* mb = (const unsigned char*)maskp;
    const int* mi = (const int*)maskp;
    const float* mf = (const float*)maskp;
    for (int i = t; i < Bn * Tn; i += blockDim.x) {
        int b = i >> 10, tt = i & (Tn - 1);
        int m;
        if (kind == 1)      m = (int)mb[i];
        else if (kind == 2) m = (mf[i] != 0.0f);
        else                m = mi[i];
        if (m) atomicMin(&s_len[b], tt);
    }
    __syncthreads();
    if (t < Bn) g_len[t] = s_len[t];
}

// ============ mma.sync GEMM: C[M,N] = A[M,K](fp16) * B[N,K](fp16)^T + bias ============
// Single-barrier multistage pipeline: wait(<=1) -> sync -> issue(c+2) -> compute(c).
// Hazard-free: stage (c+2)%3 == (c-1)%3 was last read in iter c-1; the barrier
// at iter c proves all warps finished iter c-1.
#define GST 3
#define STAGE_BYTES 32768

template<bool RELU, bool HALF_OUT>
__global__ void __launch_bounds__(256) gemm_mma(
    const __half* __restrict__ A2,
    const __half* __restrict__ B2,
    const float* __restrict__ bias,
    void* __restrict__ Cv, int N, int K2)
{
    extern __shared__ char smem[];
    uint32_t sb = smem_u32(smem);
    int tid = threadIdx.x, lane = tid & 31, w = tid >> 5;
    int m0 = blockIdx.y * 128, n0 = blockIdx.x * 128;
    int warpM = (w >> 2) * 64, warpN = (w & 3) * 32;
    const int CH = K2 >> 6;

    auto issue = [&](int c) {
        if (c < CH) {
            uint32_t base = sb + (c % GST) * STAGE_BYTES;
            long kb = (long)c * 64;
#pragma unroll
            for (int i = 0; i < 4; i++) {
                int flat = i * 256 + tid;
                int row = flat >> 3;
                int seg = flat & 7;
                uint32_t off = (uint32_t)(row * 128 + ((seg * 16) ^ ((row & 7) * 16)));
                CP_ASYNC16(base + off,         A2 + (long)(m0 + row) * K2 + kb + seg * 8);
                CP_ASYNC16(base + 16384 + off, B2 + (long)(n0 + row) * K2 + kb + seg * 8);
            }
        }
        CP_COMMIT();
    };
    issue(0); issue(1);

    float acc[4][4][4];
#pragma unroll
    for (int i = 0; i < 4; i++)
#pragma unroll
        for (int j = 0; j < 4; j++)
#pragma unroll
            for (int k = 0; k < 4; k++) acc[i][j][k] = 0.0f;

    int mrow = warpM + (lane & 7) + ((lane >> 3) & 1) * 8;
    int acol = (lane >> 4) * 16;
    int nrow = warpN + (lane & 7) + ((lane >> 4) & 1) * 8;
    int bcol = ((lane >> 3) & 1) * 16;

    for (int c = 0; c < CH; c++) {
        CP_WAIT1();
        __syncthreads();
        issue(c + 2);
        uint32_t sA = sb + (c % GST) * STAGE_BYTES;
        uint32_t sB = sA + 16384;
#pragma unroll
        for (int ks = 0; ks < 4; ks++) {
            uint32_t af[4][4];
#pragma unroll
            for (int mi = 0; mi < 4; mi++) {
                int m = mrow + mi * 16;
                uint32_t addr = sA + m * 128 + ((ks * 32 + acol) ^ ((m & 7) * 16));
                LDSM_X4(af[mi][0], af[mi][1], af[mi][2], af[mi][3], addr);
            }
            uint32_t bf[4][2];
#pragma unroll
            for (int nb = 0; nb < 2; nb++) {
                int n = nrow + nb * 16;
                uint32_t addr = sB + n * 128 + ((ks * 32 + bcol) ^ ((n & 7) * 16));
                uint32_t r0, r1, r2, r3;
                LDSM_X4(r0, r1, r2, r3, addr);
                bf[nb * 2][0] = r0;     bf[nb * 2][1] = r1;
                bf[nb * 2 + 1][0] = r2; bf[nb * 2 + 1][1] = r3;
            }
#pragma unroll
            for (int mi = 0; mi < 4; mi++)
#pragma unroll
                for (int ni = 0; ni < 4; ni++)
                    MMA16816(acc[mi][ni], af[mi], bf[ni]);
        }
    }

#pragma unroll
    for (int mi = 0; mi < 4; mi++) {
        int r = m0 + warpM + mi * 16 + (lane >> 2);
#pragma unroll
        for (int ni = 0; ni < 4; ni++) {
            int col = n0 + warpN + ni * 8 + (lane & 3) * 2;
            float b0 = bias[col], b1 = bias[col + 1];
            float v0 = acc[mi][ni][0] + b0, v1 = acc[mi][ni][1] + b1;
            float v2 = acc[mi][ni][2] + b0, v3 = acc[mi][ni][3] + b1;
            if (RELU) {
                v0 = fmaxf(v0, 0.0f); v1 = fmaxf(v1, 0.0f);
                v2 = fmaxf(v2, 0.0f); v3 = fmaxf(v3, 0.0f);
            }
            if (HALF_OUT) {
                __half* C = (__half*)Cv;
                __align__(4) __half o[2];
                o[0] = __float2half_rn(v0); o[1] = __float2half_rn(v1);
                *(uint32_t*)(C + (long)r * N + col) = *(const uint32_t*)o;
                o[0] = __float2half_rn(v2); o[1] = __float2half_rn(v3);
                *(uint32_t*)(C + (long)(r + 8) * N + col) = *(const uint32_t*)o;
            } else {
                float* C = (float*)Cv;
                float2 p0; p0.x = v0; p0.y = v1;
                float2 p1; p1.x = v2; p1.y = v3;
                *(float2*)(C + (long)r * N + col) = p0;
                *(float2*)(C + (long)(r + 8) * N + col) = p1;
            }
        }
    }
}

// ---------------- shared tile loader: 64 rows x 128B, swizzled ----------------
__device__ __forceinline__ void load_tile64x128(uint32_t dst, const __half* src,
                                                long strideHalfs, int tid)
{
#pragma unroll
    for (int i = 0; i < 2; i++) {
        int flat = i * 256 + tid;
        int row = flat >> 3;
        int seg = flat & 7;
        uint32_t off = (uint32_t)(row * 128 + ((seg * 16) ^ ((row & 7) * 16)));
        CP_ASYNC16(dst + off, src + (long)row * strideHalfs + seg * 8);
    }
}

// ============ fused flash attention: qkvh -> attnh (fp16) ============
// grid (T/128 q-blocks, B*H). 8 warps x m16 = 128 q rows. K-tiles of 64, causal.
// 3-stage K/V pipeline, single barrier per tile (same safety argument as gemm).
// smem: Q 16KB + K 3x8KB + V 3x8KB = 64KB.
__global__ void __launch_bounds__(256) fa_kernel(const __half* __restrict__ qkvh,
                                                 __half* __restrict__ attnh)
{
    int qb = blockIdx.x, bh = blockIdx.y;
    int b = bh >> 4, h = bh & 15;
    int q0 = qb * 128;
    extern __shared__ char smem[];
    uint32_t sQ = smem_u32(smem);
    uint32_t sK = sQ + 16384;
    uint32_t sV = sK + 24576;
    int tid = threadIdx.x, lane = tid & 31, w = tid >> 5;

    const __half* qbase = qkvh + (long)(b * Tn + q0) * E3n + HDn * h;
    const __half* kbase = qkvh + (long)(b * Tn) * E3n + En + HDn * h;
    const __half* vbase = qkvh + (long)(b * Tn) * E3n + 2 * En + HDn * h;
    int len = g_len[b];
    const int KT = (q0 + 127) >> 6;     // inclusive last k-tile (>=1)

    auto issue = [&](int kt) {
        if (kt <= KT) {
            uint32_t dk = sK + (kt % 3) * 8192;
            uint32_t dv = sV + (kt % 3) * 8192;
            load_tile64x128(dk, kbase + (long)kt * 64 * E3n, E3n, tid);
            load_tile64x128(dv, vbase + (long)kt * 64 * E3n, E3n, tid);
        }
        CP_COMMIT();
    };

    load_tile64x128(sQ, qbase, E3n, tid);
    load_tile64x128(sQ + 8192, qbase + (long)64 * E3n, E3n, tid);
    issue(0);          // group 0: Q + K0/V0
    issue(1);          // group 1: K1/V1

    int qrow = w * 16 + (lane >> 2);                     // row in [0,128)
    int kmax0 = min(q0 + qrow, len - 1);
    int kmax1 = min(q0 + qrow + 8, len - 1);
    int mrow = w * 16 + (lane & 7) + ((lane >> 3) & 1) * 8;  // Q A-ldsm row
    int acol = (lane >> 4) * 16;
    int nrow0 = (lane & 7) + ((lane >> 4) & 1) * 8;          // K B-ldsm row
    int bcol = ((lane >> 3) & 1) * 16;
    int wmaskref = min(q0 + w * 16, len - 1);            // min kmax over warp rows

    float m0r = -1e30f, m1r = -1e30f, l0 = 0.0f, l1 = 0.0f;
    float o[8][4];
#pragma unroll
    for (int i = 0; i < 8; i++)
#pragma unroll
        for (int j = 0; j < 4; j++) o[i][j] = 0.0f;

    for (int kt = 0; kt <= KT; kt++) {
        CP_WAIT1();
        __syncthreads();
        issue(kt + 2);
        uint32_t sk = sK + (kt % 3) * 8192;
        uint32_t sv = sV + (kt % 3) * 8192;

        // ---- S = Q . K^T : m16 x n64 per warp ----
        float c[8][4];
#pragma unroll
        for (int i = 0; i < 8; i++)
#pragma unroll
            for (int j = 0; j < 4; j++) c[i][j] = 0.0f;
#pragma unroll
        for (int ks = 0; ks < 4; ks++) {
            uint32_t af[4];
            LDSM_X4(af[0], af[1], af[2], af[3],
                    sQ + mrow * 128 + ((ks * 32 + acol) ^ ((mrow & 7) * 16)));
#pragma unroll
            for (int nb = 0; nb < 4; nb++) {
                int n = nrow0 + nb * 16;
                uint32_t r0, r1, r2, r3;
                LDSM_X4(r0, r1, r2, r3, sk + n * 128 + ((ks * 32 + bcol) ^ ((n & 7) * 16)));
                uint32_t bfa[2] = { r0, r1 }, bfb[2] = { r2, r3 };
                MMA16816(c[nb * 2], af, bfa);
                MMA16816(c[nb * 2 + 1], af, bfb);
            }
        }

        // ---- scale + mask + tile row max ----
        bool needmask = (kt * 64 + 63 > wmaskref);
        int colb = kt * 64 + (lane & 3) * 2;
        float mt0 = -1e30f, mt1 = -1e30f;
#pragma unroll
        for (int nf = 0; nf < 8; nf++) {
            c[nf][0] *= SCALE_Q; c[nf][1] *= SCALE_Q;
            c[nf][2] *= SCALE_Q; c[nf][3] *= SCALE_Q;
            if (needmask) {
                int col = colb + nf * 8;
                if (col > kmax0)     c[nf][0] = -1e30f;
                if (col + 1 > kmax0) c[nf][1] = -1e30f;
                if (col > kmax1)     c[nf][2] = -1e30f;
                if (col + 1 > kmax1) c[nf][3] = -1e30f;
            }
            mt0 = fmaxf(mt0, fmaxf(c[nf][0], c[nf][1]));
            mt1 = fmaxf(mt1, fmaxf(c[nf][2], c[nf][3]));
        }
        mt0 = fmaxf(mt0, __shfl_xor_sync(0xFFFFFFFFu, mt0, 1));
        mt0 = fmaxf(mt0, __shfl_xor_sync(0xFFFFFFFFu, mt0, 2));
        mt1 = fmaxf(mt1, __shfl_xor_sync(0xFFFFFFFFu, mt1, 1));
        mt1 = fmaxf(mt1, __shfl_xor_sync(0xFFFFFFFFu, mt1, 2));

        // ---- online softmax update ----
        float mn0 = fmaxf(m0r, mt0), mn1 = fmaxf(m1r, mt1);
        float cor0 = __expf(m0r - mn0), cor1 = __expf(m1r - mn1);
        m0r = mn0; m1r = mn1;
        float s0 = 0.0f, s1 = 0.0f;
        uint32_t ph0[8], ph1[8];
#pragma unroll
        for (int nf = 0; nf < 8; nf++) {
            float e0 = __expf(c[nf][0] - mn0);
            float e1 = __expf(c[nf][1] - mn0);
            float e2 = __expf(c[nf][2] - mn1);
            float e3 = __expf(c[nf][3] - mn1);
            s0 += e0 + e1; s1 += e2 + e3;
            __half2 hp0 = __floats2half2_rn(e0, e1);
            __half2 hp1 = __floats2half2_rn(e2, e3);
            ph0[nf] = *(uint32_t*)&hp0;
            ph1[nf] = *(uint32_t*)&hp1;
        }
        s0 += __shfl_xor_sync(0xFFFFFFFFu, s0, 1);
        s0 += __shfl_xor_sync(0xFFFFFFFFu, s0, 2);
        s1 += __shfl_xor_sync(0xFFFFFFFFu, s1, 1);
        s1 += __shfl_xor_sync(0xFFFFFFFFu, s1, 2);
        l0 = l0 * cor0 + s0;
        l1 = l1 * cor1 + s1;
#pragma unroll
        for (int nf = 0; nf < 8; nf++) {
            o[nf][0] *= cor0; o[nf][1] *= cor0;
            o[nf][2] *= cor1; o[nf][3] *= cor1;
        }

        // ---- O += P . V  (V via ldmatrix.trans from [k][d] tile) ----
#pragma unroll
        for (int kf = 0; kf < 4; kf++) {
            uint32_t a[4] = { ph0[kf * 2], ph1[kf * 2], ph0[kf * 2 + 1], ph1[kf * 2 + 1] };
            int krow = kf * 16 + ((lane >> 3) & 1) * 8 + (lane & 7);
#pragma unroll
            for (int db = 0; db < 2; db++) {
                int dcolb = ((lane >> 4) * 8 + db * 32) * 2;
                uint32_t r0, r1, r2, r3;
                LDSM_X4_T(r0, r1, r2, r3,
                          sv + krow * 128 + (dcolb ^ ((krow & 7) * 16)));
                uint32_t bfa[2] = { r0, r1 }, bfb[2] = { r2, r3 };
                MMA16816(o[db * 4 + 0], a, bfa);
                MMA16816(o[db * 4 + 1], a, bfb);
                int dcolb2 = dcolb + 32;
                LDSM_X4_T(r0, r1, r2, r3,
                          sv + krow * 128 + (dcolb2 ^ ((krow & 7) * 16)));
                uint32_t bfc[2] = { r0, r1 }, bfd[2] = { r2, r3 };
                MMA16816(o[db * 4 + 2], a, bfc);
                MMA16816(o[db * 4 + 3], a, bfd);
            }
        }
    }

    // ---- epilogue: O / l -> fp16 attn ----
    float inv0 = 1.0f / l0, inv1 = 1.0f / l1;
    long tok = (long)b * Tn + q0 + qrow;
#pragma unroll
    for (int nf = 0; nf < 8; nf++) {
        int d = h * 64 + nf * 8 + (lane & 3) * 2;
        __half2 w0 = __floats2half2_rn(o[nf][0] * inv0, o[nf][1] * inv0);
        __half2 w1 = __floats2half2_rn(o[nf][2] * inv1, o[nf][3] * inv1);
        *(uint32_t*)(attnh + tok * En + d) = *(uint32_t*)&w0;
        *(uint32_t*)(attnh + (tok + 8) * En + d) = *(uint32_t*)&w1;
    }
}

// ---------------- residual add + LayerNorm (warp-shfl reduce, 2 syncs) ----------------
__global__ void __launch_bounds__(256) ln_kernel(const float* __restrict__ res,
                                                 const float* __restrict__ y,
                                                 const float* __restrict__ w,
                                                 const float* __restrict__ bb,
                                                 float* __restrict__ out,
                                                 __half* __restrict__ outs)
{
    long r = blockIdx.x;
    int t = threadIdx.x, lane = t & 31, wid = t >> 5;
    const float* r0 = res + r * En;
    const float* y0 = y + r * En;
    __shared__ float ws[8], wss[8];
    float v[4];
    float s = 0.0f, ss = 0.0f;
#pragma unroll
    for (int i = 0; i < 4; i++) {
        int idx = t + i * 256;
        v[i] = r0[idx] + y0[idx];
        s += v[i];
        ss += v[i] * v[i];
    }
#pragma unroll
    for (int sh = 16; sh > 0; sh >>= 1) {
        s  += __shfl_xor_sync(0xFFFFFFFFu, s, sh);
        ss += __shfl_xor_sync(0xFFFFFFFFu, ss, sh);
    }
    if (lane == 0) { ws[wid] = s; wss[wid] = ss; }
    __syncthreads();
    if (wid == 0) {
        float a = (lane < 8) ? ws[lane] : 0.0f;
        float c = (lane < 8) ? wss[lane] : 0.0f;
#pragma unroll
        for (int sh = 4; sh > 0; sh >>= 1) {
            a += __shfl_xor_sync(0xFFFFFFFFu, a, sh);
            c += __shfl_xor_sync(0xFFFFFFFFu, c, sh);
        }
        if (lane == 0) { ws[0] = a; wss[0] = c; }
    }
    __syncthreads();
    float mean = ws[0] * (1.0f / En);
    float var  = wss[0] * (1.0f / En) - mean * mean;
    float inv  = rsqrtf(var + LN_EPS);
#pragma unroll
    for (int i = 0; i < 4; i++) {
        int idx = t + i * 256;
        float o = w[idx] * (v[i] - mean) * inv + bb[idx];
        out[r * En + idx] = o;
        if (outs) outs[r * En + idx] = __float2half_rn(o);
    }
}

// ---------------- launch ----------------
static inline void cvt(const float* src, __half* dst, long n) {
    long n4 = n >> 2;
    cvt_kernel<<<(unsigned)((n4 + 255) / 256), 256>>>(src, dst, n4);
}

extern "C" void kernel_launch(void* const* d_in, const int* in_sizes, int n_in,
                              void* d_out, int out_size)
{
    const float* x     = (const float*)d_in[0];
    const float* in_w  = (const float*)d_in[1];
    const float* in_b  = (const float*)d_in[2];
    const float* out_w = (const float*)d_in[3];
    const float* out_b = (const float*)d_in[4];
    const float* fc1_w = (const float*)d_in[5];
    const float* fc1_b = (const float*)d_in[6];
    const float* fc2_w = (const float*)d_in[7];
    const float* fc2_b = (const float*)d_in[8];
    const float* ln1_w = (const float*)d_in[9];
    const float* ln1_b = (const float*)d_in[10];
    const float* ln2_w = (const float*)d_in[11];
    const float* ln2_b = (const float*)d_in[12];
    const void*  pad_mask = d_in[13];
    float* out = (float*)d_out;

    float *tmp, *x1;
    cudaGetSymbolAddress((void**)&tmp, g_tmp);
    cudaGetSymbolAddress((void**)&x1,  g_x1);
    __half *qkvh, *xh, *attnh, *x1h, *ffnh, *inwh, *outwh, *fc1wh, *fc2wh;
    cudaGetSymbolAddress((void**)&qkvh,  g_qkvh);
    cudaGetSymbolAddress((void**)&xh,    g_xh);
    cudaGetSymbolAddress((void**)&attnh, g_attnh);
    cudaGetSymbolAddress((void**)&x1h,   g_x1h);
    cudaGetSymbolAddress((void**)&ffnh,  g_ffnh);
    cudaGetSymbolAddress((void**)&inwh,  g_inwh);
    cudaGetSymbolAddress((void**)&outwh, g_outwh);
    cudaGetSymbolAddress((void**)&fc1wh, g_fc1wh);
    cudaGetSymbolAddress((void**)&fc2wh, g_fc2wh);

    const int GSMEM = GST * STAGE_BYTES;   // 96 KB
    cudaFuncSetAttribute(gemm_mma<false, false>, cudaFuncAttributeMaxDynamicSharedMemorySize, GSMEM);
    cudaFuncSetAttribute(gemm_mma<false, true>,  cudaFuncAttributeMaxDynamicSharedMemorySize, GSMEM);
    cudaFuncSetAttribute(gemm_mma<true, true>,   cudaFuncAttributeMaxDynamicSharedMemorySize, GSMEM);
    cudaFuncSetAttribute(fa_kernel, cudaFuncAttributeMaxDynamicSharedMemorySize, 65536);

    // 0. sequence lengths
    len_kernel<<<1, 256>>>(pad_mask);

    // 1. QKV projection -> fp16 qkvh
    cvt(x, xh, (long)TOK * En);
    cvt(in_w, inwh, (long)E3n * En);
    gemm_mma<false, true><<<dim3(E3n / 128, TOK / 128), 256, GSMEM>>>(xh, inwh, in_b, qkvh, E3n, En);

    // 2. fused flash attention -> fp16 attnh
    fa_kernel<<<dim3(Tn / 128, BHn), 256, 65536>>>(qkvh, attnh);

    // 3. output projection
    cvt(out_w, outwh, (long)En * En);
    gemm_mma<false, false><<<dim3(En / 128, TOK / 128), 256, GSMEM>>>(attnh, outwh, out_b, tmp, En, En);

    // 4. residual + LN1
    ln_kernel<<<TOK, 256>>>(x, tmp, ln1_w, ln1_b, x1, x1h);

    // 5. FC1 + ReLU -> fp16 ffnh
    cvt(fc1_w, fc1wh, (long)FFn * En);
    gemm_mma<true, true><<<dim3(FFn / 128, TOK / 128), 256, GSMEM>>>(x1h, fc1wh, fc1_b, ffnh, FFn, En);

    // 6. FC2
    cvt(fc2_w, fc2wh, (long)En * FFn);
    gemm_mma<false, false><<<dim3(En / 128, TOK / 128), 256, GSMEM>>>(ffnh, fc2wh, fc2_b, tmp, En, FFn);

    // 7. residual + LN2 -> out
    ln_kernel<<<TOK, 256>>>(x1, tmp, ln2_w, ln2_b, out, (half*)nullptr);
}